// round 6
// baseline (speedup 1.0000x reference)
#include <cuda_runtime.h>
#include <cstdint>
#include <math.h>

#define NB    2
#define SEQL  2048
#define HEADS 16
#define HD    64
#define EMB   1024

// ---------------- scratch (device globals; no allocations) ----------------
__device__ float    g_Q[NB * HEADS * SEQL * HD];   // [n][h][s][d] tf32-rounded
__device__ float    g_K[NB * HEADS * SEQL * HD];
__device__ float    g_V[NB * HEADS * SEQL * HD];
__device__ float    g_att[NB * SEQL * EMB];        // [n][s][e] tf32-rounded
__device__ unsigned g_mbits[NB * SEQL * (SEQL / 32)];

// ---------------- helpers ----------------
__device__ __forceinline__ float tf32r(float x) {
    unsigned u;
    asm("cvt.rna.tf32.f32 %0, %1;" : "=r"(u) : "f"(x));
    return __uint_as_float(u);
}

__device__ __forceinline__ void mma_tf32(float c[4], const unsigned a[4], const unsigned b[2]) {
    asm volatile(
        "mma.sync.aligned.m16n8k8.row.col.f32.tf32.tf32.f32 "
        "{%0,%1,%2,%3}, {%4,%5,%6,%7}, {%8,%9}, {%0,%1,%2,%3};"
        : "+f"(c[0]), "+f"(c[1]), "+f"(c[2]), "+f"(c[3])
        : "r"(a[0]), "r"(a[1]), "r"(a[2]), "r"(a[3]), "r"(b[0]), "r"(b[1]));
}

// ---------------- kernel 0: pack mask to bits ----------------
__global__ void maskpack_kernel(const int* __restrict__ mask) {
    int gtid = blockIdx.x * blockDim.x + threadIdx.x;
    int word = gtid >> 5;
    int lane = gtid & 31;
    if (word >= NB * SEQL * (SEQL / 32)) return;
    int m = mask[(long)word * 32 + lane];
    unsigned bits = __ballot_sync(0xFFFFFFFFu, m != 0);
    if (lane == 0) g_mbits[word] = bits;
}

// ---------------- kernel 1: fused per-head projections ----------------
// rows r = (n*SEQL + s)*HEADS + h; input x[r*64 + d] is contiguous.
// dst[((n*HEADS+h)*SEQL + s)*64 + dd] = sum_d x[d] * W[dd][d]
__global__ void __launch_bounds__(256) proj_kernel(
    const float* __restrict__ qsrc, const float* __restrict__ ksrc, const float* __restrict__ vsrc,
    const float* __restrict__ Wq, const float* __restrict__ Wk, const float* __restrict__ Wv)
{
    const int which = blockIdx.y;
    const float* __restrict__ x = (which == 0) ? qsrc : (which == 1) ? ksrc : vsrc;
    const float* __restrict__ W = (which == 0) ? Wq : (which == 1) ? Wk : Wv;
    float* __restrict__ dst = (which == 0) ? g_Q : (which == 1) ? g_K : g_V;

    const int R0 = blockIdx.x * 64;
    const int t  = threadIdx.x;

    __shared__ float Xs[64 * 68];
    __shared__ float Ws[64 * 68];
    const int STR = 68;

    // load 64x64 input rows and 64x64 weight, float4 coalesced
#pragma unroll
    for (int i = 0; i < 4; i++) {
        int f = t + i * 256;             // 0..1023 float4 slots
        int row = f >> 4, c4 = (f & 15) << 2;
        float4 xa = *(const float4*)(x + (long)(R0 + row) * 64 + c4);
        *(float4*)(&Xs[row * STR + c4]) = xa;
        float4 wa = *(const float4*)(W + row * 64 + c4);
        *(float4*)(&Ws[row * STR + c4]) = wa;
    }
    __syncthreads();

    const int tx = t & 15, ty = t >> 4;
    float acc[4][4] = {};
#pragma unroll
    for (int kk = 0; kk < 64; kk += 4) {
        float4 a[4], b[4];
#pragma unroll
        for (int i = 0; i < 4; i++) a[i] = *(const float4*)(&Xs[(ty * 4 + i) * STR + kk]);
#pragma unroll
        for (int j = 0; j < 4; j++) b[j] = *(const float4*)(&Ws[(tx * 4 + j) * STR + kk]);
#pragma unroll
        for (int i = 0; i < 4; i++)
#pragma unroll
            for (int j = 0; j < 4; j++)
                acc[i][j] += a[i].x * b[j].x + a[i].y * b[j].y + a[i].z * b[j].z + a[i].w * b[j].w;
    }

#pragma unroll
    for (int i = 0; i < 4; i++) {
        int r = R0 + ty * 4 + i;
        int h = r & 15;                 // r = (n*SEQL+s)*16 + h
        int s = (r >> 4) & (SEQL - 1);
        int n = r >> 15;
        long ob = ((long)(n * HEADS + h) * SEQL + s) * 64;
#pragma unroll
        for (int j = 0; j < 4; j++)
            dst[ob + tx * 4 + j] = tf32r(acc[i][j]);
    }
}

// ---------------- kernel 2: flash attention (tf32 mma) ----------------
// grid: (32 q-tiles, 16 heads, 2 batch); block: 128 threads (4 warps)
// warp w owns q-rows [w*16, w*16+16) of the 64-row tile.
__global__ void __launch_bounds__(128) attn_kernel() {
    const int qt = blockIdx.x, h = blockIdx.y, n = blockIdx.z;
    const int warp = threadIdx.x >> 5, lane = threadIdx.x & 31;
    const int g = lane >> 2, tg = lane & 3;

    __shared__ float Ks[64 * 72];   // reused as P buffer after S-phase
    __shared__ float Vs[64 * 72];
    const int STR = 72;

    const float* __restrict__ Qg = g_Q + ((long)(n * HEADS + h) * SEQL + qt * 64) * 64;
    const float* __restrict__ Kg = g_K + (long)(n * HEADS + h) * SEQL * 64;
    const float* __restrict__ Vg = g_V + (long)(n * HEADS + h) * SEQL * 64;

    // Q fragments, register-resident across all k-tiles
    unsigned qa[8][4];
    const int r0 = warp * 16 + g;
#pragma unroll
    for (int kk = 0; kk < 8; kk++) {
        qa[kk][0] = __float_as_uint(Qg[(long)(r0) * 64 + kk * 8 + tg]);
        qa[kk][1] = __float_as_uint(Qg[(long)(r0 + 8) * 64 + kk * 8 + tg]);
        qa[kk][2] = __float_as_uint(Qg[(long)(r0) * 64 + kk * 8 + tg + 4]);
        qa[kk][3] = __float_as_uint(Qg[(long)(r0 + 8) * 64 + kk * 8 + tg + 4]);
    }

    float o[8][4] = {};
    const float NEG = __int_as_float(0xff800000);  // -inf
    float m_lo = NEG, m_hi = NEG, l_lo = 0.f, l_hi = 0.f;

    const int ql_lo = qt * 64 + r0;
    const int ql_hi = ql_lo + 8;
    const unsigned* __restrict__ mb_lo = g_mbits + (long)(n * SEQL + ql_lo) * (SEQL / 32);
    const unsigned* __restrict__ mb_hi = g_mbits + (long)(n * SEQL + ql_hi) * (SEQL / 32);

    const float SC = 0.03125f;           // 1/sqrt(1024)
    const float MASKED = -1e20f * SC;    // matches reference: (-1e20)/sqrt(1024)

    for (int kt = 0; kt < 32; kt++) {
        // load K and V tiles (64x64 each), coalesced float4
        const float* Ksrc = Kg + (long)kt * 64 * 64;
        const float* Vsrc = Vg + (long)kt * 64 * 64;
#pragma unroll
        for (int i = 0; i < 8; i++) {
            int f = threadIdx.x + i * 128;      // 1024 float4 slots
            int row = f >> 4, c4 = (f & 15) << 2;
            *(float4*)(&Ks[row * STR + c4]) = *(const float4*)(Ksrc + (long)row * 64 + c4);
            *(float4*)(&Vs[row * STR + c4]) = *(const float4*)(Vsrc + (long)row * 64 + c4);
        }
        __syncthreads();

        // S = Q * K^T (16 q-rows x 64 k-cols per warp)
        float s[8][4] = {};
#pragma unroll
        for (int kk = 0; kk < 8; kk++) {
#pragma unroll
            for (int nb = 0; nb < 8; nb++) {
                unsigned b[2];
                b[0] = __float_as_uint(Ks[(nb * 8 + g) * STR + kk * 8 + tg]);
                b[1] = __float_as_uint(Ks[(nb * 8 + g) * STR + kk * 8 + tg + 4]);
                mma_tf32(s[nb], qa[kk], b);
            }
        }

        // mask bits for this 64-wide tile (2 words per row)
        uint2 wlo = *(const uint2*)(mb_lo + kt * 2);
        uint2 whi = *(const uint2*)(mb_hi + kt * 2);
        uint64_t bm_lo = ((uint64_t)wlo.y << 32) | wlo.x;
        uint64_t bm_hi = ((uint64_t)whi.y << 32) | whi.x;

        // masked logits + tile row-max
        float tmax_lo = NEG, tmax_hi = NEG;
#pragma unroll
        for (int nb = 0; nb < 8; nb++) {
            int c0 = nb * 8 + tg * 2, c1 = c0 + 1;
            s[nb][0] = ((bm_lo >> c0) & 1) ? s[nb][0] * SC : MASKED;
            s[nb][1] = ((bm_lo >> c1) & 1) ? s[nb][1] * SC : MASKED;
            s[nb][2] = ((bm_hi >> c0) & 1) ? s[nb][2] * SC : MASKED;
            s[nb][3] = ((bm_hi >> c1) & 1) ? s[nb][3] * SC : MASKED;
            tmax_lo = fmaxf(tmax_lo, fmaxf(s[nb][0], s[nb][1]));
            tmax_hi = fmaxf(tmax_hi, fmaxf(s[nb][2], s[nb][3]));
        }
        // lanes tg=0..3 within the same g share a row: xor 1,2 reduce
        tmax_lo = fmaxf(tmax_lo, __shfl_xor_sync(0xFFFFFFFFu, tmax_lo, 1));
        tmax_lo = fmaxf(tmax_lo, __shfl_xor_sync(0xFFFFFFFFu, tmax_lo, 2));
        tmax_hi = fmaxf(tmax_hi, __shfl_xor_sync(0xFFFFFFFFu, tmax_hi, 1));
        tmax_hi = fmaxf(tmax_hi, __shfl_xor_sync(0xFFFFFFFFu, tmax_hi, 2));

        float mn_lo = fmaxf(m_lo, tmax_lo);
        float mn_hi = fmaxf(m_hi, tmax_hi);
        float a_lo = __expf(m_lo - mn_lo);
        float a_hi = __expf(m_hi - mn_hi);
        m_lo = mn_lo; m_hi = mn_hi;

        // probabilities (in registers, reuse s[][])
        float rs_lo = 0.f, rs_hi = 0.f;
#pragma unroll
        for (int nb = 0; nb < 8; nb++) {
            s[nb][0] = __expf(s[nb][0] - mn_lo);
            s[nb][1] = __expf(s[nb][1] - mn_lo);
            s[nb][2] = __expf(s[nb][2] - mn_hi);
            s[nb][3] = __expf(s[nb][3] - mn_hi);
            rs_lo += s[nb][0] + s[nb][1];
            rs_hi += s[nb][2] + s[nb][3];
            o[nb][0] *= a_lo; o[nb][1] *= a_lo;
            o[nb][2] *= a_hi; o[nb][3] *= a_hi;
        }
        rs_lo += __shfl_xor_sync(0xFFFFFFFFu, rs_lo, 1);
        rs_lo += __shfl_xor_sync(0xFFFFFFFFu, rs_lo, 2);
        rs_hi += __shfl_xor_sync(0xFFFFFFFFu, rs_hi, 1);
        rs_hi += __shfl_xor_sync(0xFFFFFFFFu, rs_hi, 2);
        l_lo = l_lo * a_lo + rs_lo;
        l_hi = l_hi * a_hi + rs_hi;

        __syncthreads();   // everyone done reading Ks before P overwrite

        // store P into Ks buffer (C-fragment layout to [row][col])
#pragma unroll
        for (int nb = 0; nb < 8; nb++) {
            int c0 = nb * 8 + tg * 2;
            Ks[(long)(r0) * STR + c0]     = tf32r(s[nb][0]);
            Ks[(long)(r0) * STR + c0 + 1] = tf32r(s[nb][1]);
            Ks[(long)(r0 + 8) * STR + c0]     = tf32r(s[nb][2]);
            Ks[(long)(r0 + 8) * STR + c0 + 1] = tf32r(s[nb][3]);
        }
        __syncthreads();   // P visible to all lanes

        // O += P * V   (P: 16x64 per warp, V: 64x64)
#pragma unroll
        for (int kk = 0; kk < 8; kk++) {
            unsigned pa[4];
            pa[0] = __float_as_uint(Ks[(r0) * STR + kk * 8 + tg]);
            pa[1] = __float_as_uint(Ks[(r0 + 8) * STR + kk * 8 + tg]);
            pa[2] = __float_as_uint(Ks[(r0) * STR + kk * 8 + tg + 4]);
            pa[3] = __float_as_uint(Ks[(r0 + 8) * STR + kk * 8 + tg + 4]);
#pragma unroll
            for (int nb = 0; nb < 8; nb++) {
                unsigned b[2];
                // B fragment (col-major k x n): row = k index, col = n index
                b[0] = __float_as_uint(Vs[(kk * 8 + tg) * STR + nb * 8 + g]);
                b[1] = __float_as_uint(Vs[(kk * 8 + tg + 4) * STR + nb * 8 + g]);
                mma_tf32(o[nb], pa, b);
            }
        }
        __syncthreads();   // done with Ks/Vs before next tile load
    }

    // epilogue: normalize, write att[n][q][h*64+d] (tf32-rounded for Wo GEMM)
    float inv_lo = 1.0f / l_lo;
    float inv_hi = 1.0f / l_hi;
    float* __restrict__ Og = g_att + ((long)n * SEQL + qt * 64) * EMB + h * 64;
#pragma unroll
    for (int nb = 0; nb < 8; nb++) {
        int c0 = nb * 8 + tg * 2;
        Og[(long)(r0) * EMB + c0]         = tf32r(o[nb][0] * inv_lo);
        Og[(long)(r0) * EMB + c0 + 1]     = tf32r(o[nb][1] * inv_lo);
        Og[(long)(r0 + 8) * EMB + c0]     = tf32r(o[nb][2] * inv_hi);
        Og[(long)(r0 + 8) * EMB + c0 + 1] = tf32r(o[nb][3] * inv_hi);
    }
}

// ---------------- kernel 3: output projection (tf32 mma) ----------------
// out[m][e] = sum_k att[m][k] * Wo[e][k] + bo[e];  M=4096, N=1024, K=1024
__global__ void __launch_bounds__(128) wo_kernel(
    const float* __restrict__ Wo, const float* __restrict__ bo, float* __restrict__ out)
{
    const int mrow = blockIdx.x * 64;
    const int ecol = blockIdx.y * 64;
    const int warp = threadIdx.x >> 5, lane = threadIdx.x & 31;
    const int g = lane >> 2, tg = lane & 3;

    __shared__ float As[64 * 72];
    __shared__ float Bs[64 * 72];
    const int STR = 72;

    float acc[8][4] = {};

    for (int kc = 0; kc < 16; kc++) {
#pragma unroll
        for (int i = 0; i < 8; i++) {
            int f = threadIdx.x + i * 128;
            int row = f >> 4, c4 = (f & 15) << 2;
            float4 av = *(const float4*)(g_att + (long)(mrow + row) * EMB + kc * 64 + c4);
            *(float4*)(&As[row * STR + c4]) = av;
            float4 bv = *(const float4*)(Wo + (long)(ecol + row) * EMB + kc * 64 + c4);
            bv.x = tf32r(bv.x); bv.y = tf32r(bv.y); bv.z = tf32r(bv.z); bv.w = tf32r(bv.w);
            *(float4*)(&Bs[row * STR + c4]) = bv;
        }
        __syncthreads();

#pragma unroll
        for (int kk = 0; kk < 8; kk++) {
            unsigned a[4];
            a[0] = __float_as_uint(As[(warp * 16 + g) * STR + kk * 8 + tg]);
            a[1] = __float_as_uint(As[(warp * 16 + g + 8) * STR + kk * 8 + tg]);
            a[2] = __float_as_uint(As[(warp * 16 + g) * STR + kk * 8 + tg + 4]);
            a[3] = __float_as_uint(As[(warp * 16 + g + 8) * STR + kk * 8 + tg + 4]);
#pragma unroll
            for (int nb = 0; nb < 8; nb++) {
                unsigned b[2];
                b[0] = __float_as_uint(Bs[(nb * 8 + g) * STR + kk * 8 + tg]);
                b[1] = __float_as_uint(Bs[(nb * 8 + g) * STR + kk * 8 + tg + 4]);
                mma_tf32(acc[nb], a, b);
            }
        }
        __syncthreads();
    }

    const int rlo = mrow + warp * 16 + g;
#pragma unroll
    for (int nb = 0; nb < 8; nb++) {
        int e0 = ecol + nb * 8 + tg * 2;
        float b0 = bo[e0], b1 = bo[e0 + 1];
        out[(long)rlo * EMB + e0]           = acc[nb][0] + b0;
        out[(long)rlo * EMB + e0 + 1]       = acc[nb][1] + b1;
        out[(long)(rlo + 8) * EMB + e0]     = acc[nb][2] + b0;
        out[(long)(rlo + 8) * EMB + e0 + 1] = acc[nb][3] + b1;
    }
}

// ---------------- launch ----------------
extern "C" void kernel_launch(void* const* d_in, const int* in_sizes, int n_in,
                              void* d_out, int out_size) {
    const float* vals = (const float*)d_in[0];
    const float* keys = (const float*)d_in[1];
    const float* qry  = (const float*)d_in[2];
    const int*   mask = (const int*)d_in[3];
    const float* Wv   = (const float*)d_in[4];
    const float* Wk   = (const float*)d_in[5];
    const float* Wq   = (const float*)d_in[6];
    const float* Wo   = (const float*)d_in[7];
    const float* bo   = (const float*)d_in[8];
    float* out = (float*)d_out;

    // pack mask bits: NB*SEQL*SEQL ints, 32 per warp
    long total_threads = (long)NB * SEQL * SEQL;
    maskpack_kernel<<<(unsigned)((total_threads + 255) / 256), 256>>>(mask);

    // fused projections: rows = NB*SEQL*HEADS = 65536 rows -> 1024 blocks, y = {q,k,v}
    proj_kernel<<<dim3(1024, 3), 256>>>(qry, keys, vals, Wq, Wk, Wv);

    attn_kernel<<<dim3(SEQL / 64, HEADS, NB), 128>>>();

    wo_kernel<<<dim3((NB * SEQL) / 64, EMB / 64), 128>>>(Wo, bo, out);
}

// round 9
// speedup vs baseline: 1.2379x; 1.2379x over previous
#include <cuda_runtime.h>
#include <cstdint>
#include <math.h>

#define NB    2
#define SEQL  2048
#define HEADS 16
#define HD    64
#define EMB   1024

// ---------------- scratch (device globals; no allocations) ----------------
__device__ float    g_Q[NB * HEADS * SEQL * HD];   // [n][h][s][d] tf32-rounded
__device__ float    g_K[NB * HEADS * SEQL * HD];
__device__ float    g_V[NB * HEADS * SEQL * HD];
__device__ float    g_att[NB * SEQL * EMB];        // [n][s][e] tf32-rounded
__device__ unsigned g_mbits[NB * SEQL * (SEQL / 32)];

// ---------------- helpers ----------------
__device__ __forceinline__ float tf32r(float x) {
    unsigned u;
    asm("cvt.rna.tf32.f32 %0, %1;" : "=r"(u) : "f"(x));
    return __uint_as_float(u);
}

__device__ __forceinline__ void mma_tf32(float c[4], const unsigned a[4], const unsigned b[2]) {
    asm volatile(
        "mma.sync.aligned.m16n8k8.row.col.f32.tf32.tf32.f32 "
        "{%0,%1,%2,%3}, {%4,%5,%6,%7}, {%8,%9}, {%0,%1,%2,%3};"
        : "+f"(c[0]), "+f"(c[1]), "+f"(c[2]), "+f"(c[3])
        : "r"(a[0]), "r"(a[1]), "r"(a[2]), "r"(a[3]), "r"(b[0]), "r"(b[1]));
}

// ---------------- kernel 0: pack mask to bits ----------------
__global__ void maskpack_kernel(const int* __restrict__ mask) {
    int gtid = blockIdx.x * blockDim.x + threadIdx.x;
    int word = gtid >> 5;
    int lane = gtid & 31;
    if (word >= NB * SEQL * (SEQL / 32)) return;
    int m = mask[(long)word * 32 + lane];
    unsigned bits = __ballot_sync(0xFFFFFFFFu, m != 0);
    if (lane == 0) g_mbits[word] = bits;
}

// ---------------- kernel 1: fused per-head projections ----------------
__global__ void __launch_bounds__(256) proj_kernel(
    const float* __restrict__ qsrc, const float* __restrict__ ksrc, const float* __restrict__ vsrc,
    const float* __restrict__ Wq, const float* __restrict__ Wk, const float* __restrict__ Wv)
{
    const int which = blockIdx.y;
    const float* __restrict__ x = (which == 0) ? qsrc : (which == 1) ? ksrc : vsrc;
    const float* __restrict__ W = (which == 0) ? Wq : (which == 1) ? Wk : Wv;
    float* __restrict__ dst = (which == 0) ? g_Q : (which == 1) ? g_K : g_V;

    const int R0 = blockIdx.x * 64;
    const int t  = threadIdx.x;

    __shared__ float Xs[64 * 68];
    __shared__ float Ws[64 * 68];
    const int STR = 68;

#pragma unroll
    for (int i = 0; i < 4; i++) {
        int f = t + i * 256;
        int row = f >> 4, c4 = (f & 15) << 2;
        float4 xa = *(const float4*)(x + (long)(R0 + row) * 64 + c4);
        *(float4*)(&Xs[row * STR + c4]) = xa;
        float4 wa = *(const float4*)(W + row * 64 + c4);
        *(float4*)(&Ws[row * STR + c4]) = wa;
    }
    __syncthreads();

    const int tx = t & 15, ty = t >> 4;
    float acc[4][4] = {};
#pragma unroll
    for (int kk = 0; kk < 64; kk += 4) {
        float4 a[4], b[4];
#pragma unroll
        for (int i = 0; i < 4; i++) a[i] = *(const float4*)(&Xs[(ty * 4 + i) * STR + kk]);
#pragma unroll
        for (int j = 0; j < 4; j++) b[j] = *(const float4*)(&Ws[(tx * 4 + j) * STR + kk]);
#pragma unroll
        for (int i = 0; i < 4; i++)
#pragma unroll
            for (int j = 0; j < 4; j++)
                acc[i][j] += a[i].x * b[j].x + a[i].y * b[j].y + a[i].z * b[j].z + a[i].w * b[j].w;
    }

#pragma unroll
    for (int i = 0; i < 4; i++) {
        int r = R0 + ty * 4 + i;
        int h = r & 15;
        int s = (r >> 4) & (SEQL - 1);
        int n = r >> 15;
        long ob = ((long)(n * HEADS + h) * SEQL + s) * 64;
#pragma unroll
        for (int j = 0; j < 4; j++)
            dst[ob + tx * 4 + j] = tf32r(acc[i][j]);
    }
}

// ---------------- kernel 2: flash attention (tf32 mma, m=32/warp) ----------------
// grid: (16 q-tiles of 128, 16 heads, 2 batch); block: 128 threads (4 warps)
// warp w owns q-rows [w*32, w*32+32): two m16 fragments (rows +0/+8 and +16/+24).
// k-tile = 32 cols. B fragments (K, V) reused across both m-fragments.
__global__ void __launch_bounds__(128) attn_kernel() {
    const int qt = blockIdx.x, h = blockIdx.y, n = blockIdx.z;
    const int warp = threadIdx.x >> 5, lane = threadIdx.x & 31;
    const int g = lane >> 2, tg = lane & 3;

    __shared__ float Ks[32 * 68];   // K tile: 32 k-rows x 64 d
    __shared__ float Vs[32 * 72];   // V tile: 32 k-rows x 64 d
    __shared__ float Ps[128 * 36];  // P: 128 q-rows x 32 k-cols
    const int STRK = 68, STRV = 72, STRP = 36;

    const float* __restrict__ Qg = g_Q + ((long)(n * HEADS + h) * SEQL + qt * 128) * 64;
    const float* __restrict__ Kg = g_K + (long)(n * HEADS + h) * SEQL * 64;
    const float* __restrict__ Vg = g_V + (long)(n * HEADS + h) * SEQL * 64;

    const int r0 = warp * 32 + g;

    // Q fragments for 2 m-frags, register-resident across all k-tiles (64 regs)
    unsigned qa[2][8][4];
#pragma unroll
    for (int f = 0; f < 2; f++)
#pragma unroll
        for (int kk = 0; kk < 8; kk++) {
            int ra = r0 + 16 * f;
            qa[f][kk][0] = __float_as_uint(Qg[(long)(ra)     * 64 + kk * 8 + tg]);
            qa[f][kk][1] = __float_as_uint(Qg[(long)(ra + 8) * 64 + kk * 8 + tg]);
            qa[f][kk][2] = __float_as_uint(Qg[(long)(ra)     * 64 + kk * 8 + tg + 4]);
            qa[f][kk][3] = __float_as_uint(Qg[(long)(ra + 8) * 64 + kk * 8 + tg + 4]);
        }

    float o[2][8][4] = {};
    const float NEG = __int_as_float(0xff800000);  // -inf
    float mrun[4] = {NEG, NEG, NEG, NEG};          // rows r0, r0+8, r0+16, r0+24
    float lrun[4] = {0.f, 0.f, 0.f, 0.f};

    // mask base: row (qt*128 + r0 + j*8), 64 words per row
    const unsigned* __restrict__ mbase =
        g_mbits + ((long)(n * SEQL + qt * 128 + r0)) * 64;

    const float SC = 0.03125f;           // 1/sqrt(1024)
    const float MASKED = -1e20f * SC;    // matches reference: (-1e20)/sqrt(1024)

    for (int kt = 0; kt < 64; kt++) {
        // load K and V tiles (32x64 each), coalesced float4: 512 float4 slots each
        const float* Ksrc = Kg + (long)kt * 32 * 64;
        const float* Vsrc = Vg + (long)kt * 32 * 64;
#pragma unroll
        for (int i = 0; i < 4; i++) {
            int f = threadIdx.x + i * 128;      // 0..511
            int row = f >> 4, c4 = (f & 15) << 2;
            *(float4*)(&Ks[row * STRK + c4]) = *(const float4*)(Ksrc + (long)row * 64 + c4);
            *(float4*)(&Vs[row * STRV + c4]) = *(const float4*)(Vsrc + (long)row * 64 + c4);
        }
        __syncthreads();

        // mask words for this thread's 4 rows (tile = 32 cols = 1 word)
        unsigned mw[4];
#pragma unroll
        for (int j = 0; j < 4; j++) mw[j] = mbase[j * 8 * 64 + kt];

        // S = Q * K^T : 32 q-rows x 32 k-cols per warp; B reused across m-frags
        float s[2][4][4] = {};
#pragma unroll
        for (int kk = 0; kk < 8; kk++) {
#pragma unroll
            for (int nb = 0; nb < 4; nb++) {
                unsigned b[2];
                b[0] = __float_as_uint(Ks[(nb * 8 + g) * STRK + kk * 8 + tg]);
                b[1] = __float_as_uint(Ks[(nb * 8 + g) * STRK + kk * 8 + tg + 4]);
                mma_tf32(s[0][nb], qa[0][kk], b);
                mma_tf32(s[1][nb], qa[1][kk], b);
            }
        }

        // masked logits + tile row-max (row j: f=j>>1, slots (j&1)*2..+1)
        float tmax[4] = {NEG, NEG, NEG, NEG};
#pragma unroll
        for (int nb = 0; nb < 4; nb++) {
            int c0 = nb * 8 + tg * 2, c1 = c0 + 1;
#pragma unroll
            for (int j = 0; j < 4; j++) {
                int f = j >> 1, sl = (j & 1) * 2;
                s[f][nb][sl]     = ((mw[j] >> c0) & 1) ? s[f][nb][sl]     * SC : MASKED;
                s[f][nb][sl + 1] = ((mw[j] >> c1) & 1) ? s[f][nb][sl + 1] * SC : MASKED;
                tmax[j] = fmaxf(tmax[j], fmaxf(s[f][nb][sl], s[f][nb][sl + 1]));
            }
        }

        float alpha[4];
#pragma unroll
        for (int j = 0; j < 4; j++) {
            tmax[j] = fmaxf(tmax[j], __shfl_xor_sync(0xFFFFFFFFu, tmax[j], 1));
            tmax[j] = fmaxf(tmax[j], __shfl_xor_sync(0xFFFFFFFFu, tmax[j], 2));
            float mn = fmaxf(mrun[j], tmax[j]);
            alpha[j] = __expf(mrun[j] - mn);
            mrun[j] = mn;
        }

        // exponentiate + row sums
        float rs[4] = {0.f, 0.f, 0.f, 0.f};
#pragma unroll
        for (int nb = 0; nb < 4; nb++)
#pragma unroll
            for (int f = 0; f < 2; f++) {
                s[f][nb][0] = __expf(s[f][nb][0] - mrun[2 * f]);
                s[f][nb][1] = __expf(s[f][nb][1] - mrun[2 * f]);
                s[f][nb][2] = __expf(s[f][nb][2] - mrun[2 * f + 1]);
                s[f][nb][3] = __expf(s[f][nb][3] - mrun[2 * f + 1]);
                rs[2 * f]     += s[f][nb][0] + s[f][nb][1];
                rs[2 * f + 1] += s[f][nb][2] + s[f][nb][3];
            }
#pragma unroll
        for (int j = 0; j < 4; j++) {
            rs[j] += __shfl_xor_sync(0xFFFFFFFFu, rs[j], 1);
            rs[j] += __shfl_xor_sync(0xFFFFFFFFu, rs[j], 2);
            lrun[j] = lrun[j] * alpha[j] + rs[j];
        }

        // rescale O
#pragma unroll
        for (int f = 0; f < 2; f++)
#pragma unroll
            for (int nb = 0; nb < 8; nb++) {
                o[f][nb][0] *= alpha[2 * f];     o[f][nb][1] *= alpha[2 * f];
                o[f][nb][2] *= alpha[2 * f + 1]; o[f][nb][3] *= alpha[2 * f + 1];
            }

        // store P (warp-private rows -> only __syncwarp needed)
#pragma unroll
        for (int f = 0; f < 2; f++)
#pragma unroll
            for (int nb = 0; nb < 4; nb++) {
                int ra = r0 + 16 * f;
                int c0 = nb * 8 + tg * 2;
                *(float2*)(&Ps[(ra)     * STRP + c0]) = make_float2(tf32r(s[f][nb][0]), tf32r(s[f][nb][1]));
                *(float2*)(&Ps[(ra + 8) * STRP + c0]) = make_float2(tf32r(s[f][nb][2]), tf32r(s[f][nb][3]));
            }
        __syncwarp();

        // O += P * V : per warp 32 q-rows x 64 d, k-range 32
#pragma unroll
        for (int kk2 = 0; kk2 < 4; kk2++) {
            unsigned pa0[4], pa1[4];
            pa0[0] = __float_as_uint(Ps[(r0)      * STRP + kk2 * 8 + tg]);
            pa0[1] = __float_as_uint(Ps[(r0 + 8)  * STRP + kk2 * 8 + tg]);
            pa0[2] = __float_as_uint(Ps[(r0)      * STRP + kk2 * 8 + tg + 4]);
            pa0[3] = __float_as_uint(Ps[(r0 + 8)  * STRP + kk2 * 8 + tg + 4]);
            pa1[0] = __float_as_uint(Ps[(r0 + 16) * STRP + kk2 * 8 + tg]);
            pa1[1] = __float_as_uint(Ps[(r0 + 24) * STRP + kk2 * 8 + tg]);
            pa1[2] = __float_as_uint(Ps[(r0 + 16) * STRP + kk2 * 8 + tg + 4]);
            pa1[3] = __float_as_uint(Ps[(r0 + 24) * STRP + kk2 * 8 + tg + 4]);
#pragma unroll
            for (int nb = 0; nb < 8; nb++) {
                unsigned b[2];
                b[0] = __float_as_uint(Vs[(kk2 * 8 + tg)     * STRV + nb * 8 + g]);
                b[1] = __float_as_uint(Vs[(kk2 * 8 + tg + 4) * STRV + nb * 8 + g]);
                mma_tf32(o[0][nb], pa0, b);
                mma_tf32(o[1][nb], pa1, b);
            }
        }
        __syncthreads();   // K/V/P tiles consumed before next fill
    }

    // epilogue: normalize, write att[n][q][h*64+d] (tf32-rounded for Wo GEMM)
    float inv[4];
#pragma unroll
    for (int j = 0; j < 4; j++) inv[j] = 1.0f / lrun[j];

    float* __restrict__ Og = g_att + ((long)n * SEQL + qt * 128) * EMB + h * 64;
#pragma unroll
    for (int f = 0; f < 2; f++)
#pragma unroll
        for (int nb = 0; nb < 8; nb++) {
            int ra = r0 + 16 * f;
            int c0 = nb * 8 + tg * 2;
            Og[(long)(ra)     * EMB + c0]     = tf32r(o[f][nb][0] * inv[2 * f]);
            Og[(long)(ra)     * EMB + c0 + 1] = tf32r(o[f][nb][1] * inv[2 * f]);
            Og[(long)(ra + 8) * EMB + c0]     = tf32r(o[f][nb][2] * inv[2 * f + 1]);
            Og[(long)(ra + 8) * EMB + c0 + 1] = tf32r(o[f][nb][3] * inv[2 * f + 1]);
        }
}

// ---------------- kernel 3: output projection (tf32 mma, m=32/warp) ----------------
// out[m][e] = sum_k att[m][k] * Wo[e][k] + bo[e];  M=4096, N=1024, K=1024
// block = 128 threads, tile 128x64; warp = 32x64 (2 m-frags), B reused across frags.
__global__ void __launch_bounds__(128) wo_kernel(
    const float* __restrict__ Wo, const float* __restrict__ bo, float* __restrict__ out)
{
    const int mrow = blockIdx.x * 128;
    const int ecol = blockIdx.y * 64;
    const int warp = threadIdx.x >> 5, lane = threadIdx.x & 31;
    const int g = lane >> 2, tg = lane & 3;

    __shared__ float As[128 * 68];  // 128 rows x 64 cols = 2048 float4 slots
    __shared__ float Bs[64 * 68];   //  64 rows x 64 cols = 1024 float4 slots
    const int STR = 68;

    float acc[2][8][4] = {};
    const int br = warp * 32 + g;

    for (int kc = 0; kc < 16; kc++) {
        // fill As (128x64): 2048 slots = 16 iters * 128 threads  [bug fixed]
#pragma unroll
        for (int i = 0; i < 16; i++) {
            int f = threadIdx.x + i * 128;   // 0..2047
            int row = f >> 4, c4 = (f & 15) << 2;
            *(float4*)(&As[row * STR + c4]) =
                *(const float4*)(g_att + (long)(mrow + row) * EMB + kc * 64 + c4);
        }
        // fill Bs (64x64): 1024 slots = 8 iters * 128 threads   [bug fixed]
#pragma unroll
        for (int i = 0; i < 8; i++) {
            int f = threadIdx.x + i * 128;   // 0..1023
            int row = f >> 4, c4 = (f & 15) << 2;
            float4 bv = *(const float4*)(Wo + (long)(ecol + row) * EMB + kc * 64 + c4);
            bv.x = tf32r(bv.x); bv.y = tf32r(bv.y); bv.z = tf32r(bv.z); bv.w = tf32r(bv.w);
            *(float4*)(&Bs[row * STR + c4]) = bv;
        }
        __syncthreads();

#pragma unroll
        for (int kk = 0; kk < 8; kk++) {
            unsigned a0[4], a1[4];
            a0[0] = __float_as_uint(As[(br)      * STR + kk * 8 + tg]);
            a0[1] = __float_as_uint(As[(br + 8)  * STR + kk * 8 + tg]);
            a0[2] = __float_as_uint(As[(br)      * STR + kk * 8 + tg + 4]);
            a0[3] = __float_as_uint(As[(br + 8)  * STR + kk * 8 + tg + 4]);
            a1[0] = __float_as_uint(As[(br + 16) * STR + kk * 8 + tg]);
            a1[1] = __float_as_uint(As[(br + 24) * STR + kk * 8 + tg]);
            a1[2] = __float_as_uint(As[(br + 16) * STR + kk * 8 + tg + 4]);
            a1[3] = __float_as_uint(As[(br + 24) * STR + kk * 8 + tg + 4]);
#pragma unroll
            for (int nb = 0; nb < 8; nb++) {
                unsigned b[2];
                b[0] = __float_as_uint(Bs[(nb * 8 + g) * STR + kk * 8 + tg]);
                b[1] = __float_as_uint(Bs[(nb * 8 + g) * STR + kk * 8 + tg + 4]);
                mma_tf32(acc[0][nb], a0, b);
                mma_tf32(acc[1][nb], a1, b);
            }
        }
        __syncthreads();
    }

#pragma unroll
    for (int f = 0; f < 2; f++)
#pragma unroll
        for (int nb = 0; nb < 8; nb++) {
            int row = mrow + br + 16 * f;
            int e0 = ecol + nb * 8 + tg * 2;
            float b0 = bo[e0], b1 = bo[e0 + 1];
            out[(long)(row)     * EMB + e0]     = acc[f][nb][0] + b0;
            out[(long)(row)     * EMB + e0 + 1] = acc[f][nb][1] + b1;
            out[(long)(row + 8) * EMB + e0]     = acc[f][nb][2] + b0;
            out[(long)(row + 8) * EMB + e0 + 1] = acc[f][nb][3] + b1;
        }
}

// ---------------- launch ----------------
extern "C" void kernel_launch(void* const* d_in, const int* in_sizes, int n_in,
                              void* d_out, int out_size) {
    const float* vals = (const float*)d_in[0];
    const float* keys = (const float*)d_in[1];
    const float* qry  = (const float*)d_in[2];
    const int*   mask = (const int*)d_in[3];
    const float* Wv   = (const float*)d_in[4];
    const float* Wk   = (const float*)d_in[5];
    const float* Wq   = (const float*)d_in[6];
    const float* Wo   = (const float*)d_in[7];
    const float* bo   = (const float*)d_in[8];
    float* out = (float*)d_out;

    long total_threads = (long)NB * SEQL * SEQL;
    maskpack_kernel<<<(unsigned)((total_threads + 255) / 256), 256>>>(mask);

    proj_kernel<<<dim3(1024, 3), 256>>>(qry, keys, vals, Wq, Wk, Wv);

    attn_kernel<<<dim3(SEQL / 128, HEADS, NB), 128>>>();

    wo_kernel<<<dim3((NB * SEQL) / 128, EMB / 64), 128>>>(Wo, bo, out);
}

// round 10
// speedup vs baseline: 1.5064x; 1.2169x over previous
#include <cuda_runtime.h>
#include <cstdint>
#include <math.h>

#define NB    2
#define SEQL  2048
#define HEADS 16
#define HD    64
#define EMB   1024

// ---------------- scratch (device globals; no allocations) ----------------
__device__ float    g_Q[NB * HEADS * SEQL * HD];   // [n][h][s][d] tf32-rounded
__device__ float    g_K[NB * HEADS * SEQL * HD];
__device__ float    g_V[NB * HEADS * SEQL * HD];
__device__ float    g_att[NB * SEQL * EMB];        // [n][s][e] tf32-rounded
__device__ unsigned g_mbits[NB * SEQL * (SEQL / 32)];

// ---------------- helpers ----------------
__device__ __forceinline__ float tf32r(float x) {
    unsigned u;
    asm("cvt.rna.tf32.f32 %0, %1;" : "=r"(u) : "f"(x));
    return __uint_as_float(u);
}

__device__ __forceinline__ void mma_tf32(float c[4], const unsigned a[4], const unsigned b[2]) {
    asm volatile(
        "mma.sync.aligned.m16n8k8.row.col.f32.tf32.tf32.f32 "
        "{%0,%1,%2,%3}, {%4,%5,%6,%7}, {%8,%9}, {%0,%1,%2,%3};"
        : "+f"(c[0]), "+f"(c[1]), "+f"(c[2]), "+f"(c[3])
        : "r"(a[0]), "r"(a[1]), "r"(a[2]), "r"(a[3]), "r"(b[0]), "r"(b[1]));
}

// ---------------- kernel 0: pack mask to bits ----------------
__global__ void maskpack_kernel(const int* __restrict__ mask) {
    int gtid = blockIdx.x * blockDim.x + threadIdx.x;
    int word = gtid >> 5;
    int lane = gtid & 31;
    if (word >= NB * SEQL * (SEQL / 32)) return;
    int m = mask[(long)word * 32 + lane];
    unsigned bits = __ballot_sync(0xFFFFFFFFu, m != 0);
    if (lane == 0) g_mbits[word] = bits;
}

// ---------------- kernel 1: fused per-head projections (tf32 mma) ----------------
// rows r = (n*SEQL + s)*HEADS + h; input x[r*64 + d] contiguous.
// dst[((n*HEADS+h)*SEQL + s)*64 + e] = sum_d x[d] * W[e][d]
// GEMM: M=65536, N=64, K=64. Block tile 128x64, 4 warps, warp = 32 rows (2 m-frags).
__global__ void __launch_bounds__(128) proj_kernel(
    const float* __restrict__ qsrc, const float* __restrict__ ksrc, const float* __restrict__ vsrc,
    const float* __restrict__ Wq, const float* __restrict__ Wk, const float* __restrict__ Wv)
{
    const int which = blockIdx.y;
    const float* __restrict__ x = (which == 0) ? qsrc : (which == 1) ? ksrc : vsrc;
    const float* __restrict__ W = (which == 0) ? Wq : (which == 1) ? Wk : Wv;
    float* __restrict__ dst = (which == 0) ? g_Q : (which == 1) ? g_K : g_V;

    const int mrow = blockIdx.x * 128;
    const int warp = threadIdx.x >> 5, lane = threadIdx.x & 31;
    const int g = lane >> 2, tg = lane & 3;

    __shared__ float Xs[128 * 68];
    __shared__ float Ws[64 * 68];
    const int STR = 68;

    // fill Xs (128x64): 2048 float4 slots, tf32-rounded
#pragma unroll
    for (int i = 0; i < 16; i++) {
        int f = threadIdx.x + i * 128;
        int row = f >> 4, c4 = (f & 15) << 2;
        float4 v = *(const float4*)(x + (long)(mrow + row) * 64 + c4);
        v.x = tf32r(v.x); v.y = tf32r(v.y); v.z = tf32r(v.z); v.w = tf32r(v.w);
        *(float4*)(&Xs[row * STR + c4]) = v;
    }
    // fill Ws (64x64): 1024 float4 slots, tf32-rounded
#pragma unroll
    for (int i = 0; i < 8; i++) {
        int f = threadIdx.x + i * 128;
        int row = f >> 4, c4 = (f & 15) << 2;
        float4 v = *(const float4*)(W + (long)row * 64 + c4);
        v.x = tf32r(v.x); v.y = tf32r(v.y); v.z = tf32r(v.z); v.w = tf32r(v.w);
        *(float4*)(&Ws[row * STR + c4]) = v;
    }
    __syncthreads();

    float acc[2][8][4] = {};
    const int br = warp * 32 + g;

#pragma unroll
    for (int kk = 0; kk < 8; kk++) {
        unsigned a0[4], a1[4];
        a0[0] = __float_as_uint(Xs[(br)      * STR + kk * 8 + tg]);
        a0[1] = __float_as_uint(Xs[(br + 8)  * STR + kk * 8 + tg]);
        a0[2] = __float_as_uint(Xs[(br)      * STR + kk * 8 + tg + 4]);
        a0[3] = __float_as_uint(Xs[(br + 8)  * STR + kk * 8 + tg + 4]);
        a1[0] = __float_as_uint(Xs[(br + 16) * STR + kk * 8 + tg]);
        a1[1] = __float_as_uint(Xs[(br + 24) * STR + kk * 8 + tg]);
        a1[2] = __float_as_uint(Xs[(br + 16) * STR + kk * 8 + tg + 4]);
        a1[3] = __float_as_uint(Xs[(br + 24) * STR + kk * 8 + tg + 4]);
#pragma unroll
        for (int nb = 0; nb < 8; nb++) {
            unsigned b[2];
            b[0] = __float_as_uint(Ws[(nb * 8 + g) * STR + kk * 8 + tg]);
            b[1] = __float_as_uint(Ws[(nb * 8 + g) * STR + kk * 8 + tg + 4]);
            mma_tf32(acc[0][nb], a0, b);
            mma_tf32(acc[1][nb], a1, b);
        }
    }

    // write out with [n][h][s][d] permutation, tf32-rounded
#pragma unroll
    for (int f = 0; f < 2; f++)
#pragma unroll
        for (int half = 0; half < 2; half++) {
            int r = mrow + br + 16 * f + 8 * half;
            int h = r & 15;
            int s = (r >> 4) & (SEQL - 1);
            int n = r >> 15;
            long ob = ((long)(n * HEADS + h) * SEQL + s) * 64;
#pragma unroll
            for (int nb = 0; nb < 8; nb++) {
                int c0 = nb * 8 + tg * 2;
                float2 v = make_float2(tf32r(acc[f][nb][2 * half]),
                                       tf32r(acc[f][nb][2 * half + 1]));
                *(float2*)(dst + ob + c0) = v;
            }
        }
}

// ---------------- kernel 2: flash attention (tf32 mma, m=32/warp, reg-prefetch) ----------------
// grid: (16 q-tiles of 128, 16 heads, 2 batch); block: 128 threads (4 warps)
// warp w owns q-rows [w*32, w*32+32): two m16 fragments. k-tile = 32.
// K/V tiles are prefetched into registers for tile kt+1 while computing tile kt.
__global__ void __launch_bounds__(128) attn_kernel() {
    const int qt = blockIdx.x, h = blockIdx.y, n = blockIdx.z;
    const int warp = threadIdx.x >> 5, lane = threadIdx.x & 31;
    const int g = lane >> 2, tg = lane & 3;

    __shared__ float Ks[32 * 68];   // K tile: 32 k-rows x 64 d
    __shared__ float Vs[32 * 72];   // V tile: 32 k-rows x 64 d
    __shared__ float Ps[128 * 36];  // P: 128 q-rows x 32 k-cols
    const int STRK = 68, STRV = 72, STRP = 36;

    const float* __restrict__ Qg = g_Q + ((long)(n * HEADS + h) * SEQL + qt * 128) * 64;
    const float* __restrict__ Kg = g_K + (long)(n * HEADS + h) * SEQL * 64;
    const float* __restrict__ Vg = g_V + (long)(n * HEADS + h) * SEQL * 64;

    const int r0 = warp * 32 + g;

    // per-thread fill coordinates (4 float4 slots each for K and V)
    int frow[4], fc4[4];
#pragma unroll
    for (int i = 0; i < 4; i++) {
        int f = threadIdx.x + i * 128;      // 0..511
        frow[i] = f >> 4;
        fc4[i]  = (f & 15) << 2;
    }

    // Q fragments for 2 m-frags, register-resident across all k-tiles (64 regs)
    unsigned qa[2][8][4];
#pragma unroll
    for (int f = 0; f < 2; f++)
#pragma unroll
        for (int kk = 0; kk < 8; kk++) {
            int ra = r0 + 16 * f;
            qa[f][kk][0] = __float_as_uint(Qg[(long)(ra)     * 64 + kk * 8 + tg]);
            qa[f][kk][1] = __float_as_uint(Qg[(long)(ra + 8) * 64 + kk * 8 + tg]);
            qa[f][kk][2] = __float_as_uint(Qg[(long)(ra)     * 64 + kk * 8 + tg + 4]);
            qa[f][kk][3] = __float_as_uint(Qg[(long)(ra + 8) * 64 + kk * 8 + tg + 4]);
        }

    float o[2][8][4] = {};
    const float NEG = __int_as_float(0xff800000);  // -inf
    float mrun[4] = {NEG, NEG, NEG, NEG};          // rows r0, r0+8, r0+16, r0+24
    float lrun[4] = {0.f, 0.f, 0.f, 0.f};

    const unsigned* __restrict__ mbase =
        g_mbits + ((long)(n * SEQL + qt * 128 + r0)) * 64;

    const float SC = 0.03125f;           // 1/sqrt(1024)
    const float MASKED = -1e20f * SC;    // matches reference: (-1e20)/sqrt(1024)

    // prologue: prefetch tile 0 into registers
    float4 kr[4], vr[4];
#pragma unroll
    for (int i = 0; i < 4; i++) {
        kr[i] = *(const float4*)(Kg + (long)frow[i] * 64 + fc4[i]);
        vr[i] = *(const float4*)(Vg + (long)frow[i] * 64 + fc4[i]);
    }

    for (int kt = 0; kt < 64; kt++) {
        // commit prefetched registers to smem
#pragma unroll
        for (int i = 0; i < 4; i++) {
            *(float4*)(&Ks[frow[i] * STRK + fc4[i]]) = kr[i];
            *(float4*)(&Vs[frow[i] * STRV + fc4[i]]) = vr[i];
        }
        __syncthreads();

        // issue prefetch for next tile (latency hidden by compute below)
        if (kt + 1 < 64) {
            const float* Ksrc = Kg + (long)(kt + 1) * 32 * 64;
            const float* Vsrc = Vg + (long)(kt + 1) * 32 * 64;
#pragma unroll
            for (int i = 0; i < 4; i++) {
                kr[i] = *(const float4*)(Ksrc + (long)frow[i] * 64 + fc4[i]);
                vr[i] = *(const float4*)(Vsrc + (long)frow[i] * 64 + fc4[i]);
            }
        }

        // mask words for this thread's 4 rows (tile = 32 cols = 1 word)
        unsigned mw[4];
#pragma unroll
        for (int j = 0; j < 4; j++) mw[j] = mbase[j * 8 * 64 + kt];

        // S = Q * K^T : 32 q-rows x 32 k-cols per warp; B reused across m-frags
        float s[2][4][4] = {};
#pragma unroll
        for (int kk = 0; kk < 8; kk++) {
#pragma unroll
            for (int nb = 0; nb < 4; nb++) {
                unsigned b[2];
                b[0] = __float_as_uint(Ks[(nb * 8 + g) * STRK + kk * 8 + tg]);
                b[1] = __float_as_uint(Ks[(nb * 8 + g) * STRK + kk * 8 + tg + 4]);
                mma_tf32(s[0][nb], qa[0][kk], b);
                mma_tf32(s[1][nb], qa[1][kk], b);
            }
        }

        // masked logits + tile row-max (row j: f=j>>1, slots (j&1)*2..+1)
        float tmax[4] = {NEG, NEG, NEG, NEG};
#pragma unroll
        for (int nb = 0; nb < 4; nb++) {
            int c0 = nb * 8 + tg * 2, c1 = c0 + 1;
#pragma unroll
            for (int j = 0; j < 4; j++) {
                int f = j >> 1, sl = (j & 1) * 2;
                s[f][nb][sl]     = ((mw[j] >> c0) & 1) ? s[f][nb][sl]     * SC : MASKED;
                s[f][nb][sl + 1] = ((mw[j] >> c1) & 1) ? s[f][nb][sl + 1] * SC : MASKED;
                tmax[j] = fmaxf(tmax[j], fmaxf(s[f][nb][sl], s[f][nb][sl + 1]));
            }
        }

        float alpha[4];
#pragma unroll
        for (int j = 0; j < 4; j++) {
            tmax[j] = fmaxf(tmax[j], __shfl_xor_sync(0xFFFFFFFFu, tmax[j], 1));
            tmax[j] = fmaxf(tmax[j], __shfl_xor_sync(0xFFFFFFFFu, tmax[j], 2));
            float mn = fmaxf(mrun[j], tmax[j]);
            alpha[j] = __expf(mrun[j] - mn);
            mrun[j] = mn;
        }

        // exponentiate + row sums
        float rs[4] = {0.f, 0.f, 0.f, 0.f};
#pragma unroll
        for (int nb = 0; nb < 4; nb++)
#pragma unroll
            for (int f = 0; f < 2; f++) {
                s[f][nb][0] = __expf(s[f][nb][0] - mrun[2 * f]);
                s[f][nb][1] = __expf(s[f][nb][1] - mrun[2 * f]);
                s[f][nb][2] = __expf(s[f][nb][2] - mrun[2 * f + 1]);
                s[f][nb][3] = __expf(s[f][nb][3] - mrun[2 * f + 1]);
                rs[2 * f]     += s[f][nb][0] + s[f][nb][1];
                rs[2 * f + 1] += s[f][nb][2] + s[f][nb][3];
            }
#pragma unroll
        for (int j = 0; j < 4; j++) {
            rs[j] += __shfl_xor_sync(0xFFFFFFFFu, rs[j], 1);
            rs[j] += __shfl_xor_sync(0xFFFFFFFFu, rs[j], 2);
            lrun[j] = lrun[j] * alpha[j] + rs[j];
        }

        // rescale O
#pragma unroll
        for (int f = 0; f < 2; f++)
#pragma unroll
            for (int nb = 0; nb < 8; nb++) {
                o[f][nb][0] *= alpha[2 * f];     o[f][nb][1] *= alpha[2 * f];
                o[f][nb][2] *= alpha[2 * f + 1]; o[f][nb][3] *= alpha[2 * f + 1];
            }

        // store P (warp-private rows -> only __syncwarp needed)
#pragma unroll
        for (int f = 0; f < 2; f++)
#pragma unroll
            for (int nb = 0; nb < 4; nb++) {
                int ra = r0 + 16 * f;
                int c0 = nb * 8 + tg * 2;
                *(float2*)(&Ps[(ra)     * STRP + c0]) = make_float2(tf32r(s[f][nb][0]), tf32r(s[f][nb][1]));
                *(float2*)(&Ps[(ra + 8) * STRP + c0]) = make_float2(tf32r(s[f][nb][2]), tf32r(s[f][nb][3]));
            }
        __syncwarp();

        // O += P * V : per warp 32 q-rows x 64 d, k-range 32
#pragma unroll
        for (int kk2 = 0; kk2 < 4; kk2++) {
            unsigned pa0[4], pa1[4];
            pa0[0] = __float_as_uint(Ps[(r0)      * STRP + kk2 * 8 + tg]);
            pa0[1] = __float_as_uint(Ps[(r0 + 8)  * STRP + kk2 * 8 + tg]);
            pa0[2] = __float_as_uint(Ps[(r0)      * STRP + kk2 * 8 + tg + 4]);
            pa0[3] = __float_as_uint(Ps[(r0 + 8)  * STRP + kk2 * 8 + tg + 4]);
            pa1[0] = __float_as_uint(Ps[(r0 + 16) * STRP + kk2 * 8 + tg]);
            pa1[1] = __float_as_uint(Ps[(r0 + 24) * STRP + kk2 * 8 + tg]);
            pa1[2] = __float_as_uint(Ps[(r0 + 16) * STRP + kk2 * 8 + tg + 4]);
            pa1[3] = __float_as_uint(Ps[(r0 + 24) * STRP + kk2 * 8 + tg + 4]);
#pragma unroll
            for (int nb = 0; nb < 8; nb++) {
                unsigned b[2];
                b[0] = __float_as_uint(Vs[(kk2 * 8 + tg)     * STRV + nb * 8 + g]);
                b[1] = __float_as_uint(Vs[(kk2 * 8 + tg + 4) * STRV + nb * 8 + g]);
                mma_tf32(o[0][nb], pa0, b);
                mma_tf32(o[1][nb], pa1, b);
            }
        }
        __syncthreads();   // K/V/P tiles consumed before next commit
    }

    // epilogue: normalize, write att[n][q][h*64+d] (tf32-rounded for Wo GEMM)
    float inv[4];
#pragma unroll
    for (int j = 0; j < 4; j++) inv[j] = 1.0f / lrun[j];

    float* __restrict__ Og = g_att + ((long)n * SEQL + qt * 128) * EMB + h * 64;
#pragma unroll
    for (int f = 0; f < 2; f++)
#pragma unroll
        for (int nb = 0; nb < 8; nb++) {
            int ra = r0 + 16 * f;
            int c0 = nb * 8 + tg * 2;
            Og[(long)(ra)     * EMB + c0]     = tf32r(o[f][nb][0] * inv[2 * f]);
            Og[(long)(ra)     * EMB + c0 + 1] = tf32r(o[f][nb][1] * inv[2 * f]);
            Og[(long)(ra + 8) * EMB + c0]     = tf32r(o[f][nb][2] * inv[2 * f + 1]);
            Og[(long)(ra + 8) * EMB + c0 + 1] = tf32r(o[f][nb][3] * inv[2 * f + 1]);
        }
}

// ---------------- kernel 3: output projection (tf32 mma, m=32/warp) ----------------
// out[m][e] = sum_k att[m][k] * Wo[e][k] + bo[e];  M=4096, N=1024, K=1024
__global__ void __launch_bounds__(128) wo_kernel(
    const float* __restrict__ Wo, const float* __restrict__ bo, float* __restrict__ out)
{
    const int mrow = blockIdx.x * 128;
    const int ecol = blockIdx.y * 64;
    const int warp = threadIdx.x >> 5, lane = threadIdx.x & 31;
    const int g = lane >> 2, tg = lane & 3;

    __shared__ float As[128 * 68];
    __shared__ float Bs[64 * 68];
    const int STR = 68;

    float acc[2][8][4] = {};
    const int br = warp * 32 + g;

    for (int kc = 0; kc < 16; kc++) {
#pragma unroll
        for (int i = 0; i < 16; i++) {
            int f = threadIdx.x + i * 128;
            int row = f >> 4, c4 = (f & 15) << 2;
            *(float4*)(&As[row * STR + c4]) =
                *(const float4*)(g_att + (long)(mrow + row) * EMB + kc * 64 + c4);
        }
#pragma unroll
        for (int i = 0; i < 8; i++) {
            int f = threadIdx.x + i * 128;
            int row = f >> 4, c4 = (f & 15) << 2;
            float4 bv = *(const float4*)(Wo + (long)(ecol + row) * EMB + kc * 64 + c4);
            bv.x = tf32r(bv.x); bv.y = tf32r(bv.y); bv.z = tf32r(bv.z); bv.w = tf32r(bv.w);
            *(float4*)(&Bs[row * STR + c4]) = bv;
        }
        __syncthreads();

#pragma unroll
        for (int kk = 0; kk < 8; kk++) {
            unsigned a0[4], a1[4];
            a0[0] = __float_as_uint(As[(br)      * STR + kk * 8 + tg]);
            a0[1] = __float_as_uint(As[(br + 8)  * STR + kk * 8 + tg]);
            a0[2] = __float_as_uint(As[(br)      * STR + kk * 8 + tg + 4]);
            a0[3] = __float_as_uint(As[(br + 8)  * STR + kk * 8 + tg + 4]);
            a1[0] = __float_as_uint(As[(br + 16) * STR + kk * 8 + tg]);
            a1[1] = __float_as_uint(As[(br + 24) * STR + kk * 8 + tg]);
            a1[2] = __float_as_uint(As[(br + 16) * STR + kk * 8 + tg + 4]);
            a1[3] = __float_as_uint(As[(br + 24) * STR + kk * 8 + tg + 4]);
#pragma unroll
            for (int nb = 0; nb < 8; nb++) {
                unsigned b[2];
                b[0] = __float_as_uint(Bs[(nb * 8 + g) * STR + kk * 8 + tg]);
                b[1] = __float_as_uint(Bs[(nb * 8 + g) * STR + kk * 8 + tg + 4]);
                mma_tf32(acc[0][nb], a0, b);
                mma_tf32(acc[1][nb], a1, b);
            }
        }
        __syncthreads();
    }

#pragma unroll
    for (int f = 0; f < 2; f++)
#pragma unroll
        for (int nb = 0; nb < 8; nb++) {
            int row = mrow + br + 16 * f;
            int e0 = ecol + nb * 8 + tg * 2;
            float b0 = bo[e0], b1 = bo[e0 + 1];
            out[(long)(row)     * EMB + e0]     = acc[f][nb][0] + b0;
            out[(long)(row)     * EMB + e0 + 1] = acc[f][nb][1] + b1;
            out[(long)(row + 8) * EMB + e0]     = acc[f][nb][2] + b0;
            out[(long)(row + 8) * EMB + e0 + 1] = acc[f][nb][3] + b1;
        }
}

// ---------------- launch ----------------
extern "C" void kernel_launch(void* const* d_in, const int* in_sizes, int n_in,
                              void* d_out, int out_size) {
    const float* vals = (const float*)d_in[0];
    const float* keys = (const float*)d_in[1];
    const float* qry  = (const float*)d_in[2];
    const int*   mask = (const int*)d_in[3];
    const float* Wv   = (const float*)d_in[4];
    const float* Wk   = (const float*)d_in[5];
    const float* Wq   = (const float*)d_in[6];
    const float* Wo   = (const float*)d_in[7];
    const float* bo   = (const float*)d_in[8];
    float* out = (float*)d_out;

    long total_threads = (long)NB * SEQL * SEQL;
    maskpack_kernel<<<(unsigned)((total_threads + 255) / 256), 256>>>(mask);

    // mma projections: 65536 rows / 128 = 512 blocks, y = {q,k,v}
    proj_kernel<<<dim3(512, 3), 128>>>(qry, keys, vals, Wq, Wk, Wv);

    attn_kernel<<<dim3(SEQL / 128, HEADS, NB), 128>>>();

    wo_kernel<<<dim3((NB * SEQL) / 128, EMB / 64), 128>>>(Wo, bo, out);
}

// round 12
// speedup vs baseline: 1.5147x; 1.0055x over previous
#include <cuda_runtime.h>
#include <cuda_pipeline.h>
#include <cstdint>
#include <math.h>

#define NB    2
#define SEQL  2048
#define HEADS 16
#define HD    64
#define EMB   1024

// ---------------- scratch (device globals; no allocations) ----------------
__device__ float    g_Q[NB * HEADS * SEQL * HD];   // [n][h][s][d] tf32-rounded
__device__ float    g_K[NB * HEADS * SEQL * HD];
__device__ float    g_V[NB * HEADS * SEQL * HD];
__device__ float    g_att[NB * SEQL * EMB];        // [n][s][e] tf32-rounded
__device__ unsigned g_mbits[NB * SEQL * (SEQL / 32)];

// ---------------- helpers ----------------
__device__ __forceinline__ float tf32r(float x) {
    unsigned u;
    asm("cvt.rna.tf32.f32 %0, %1;" : "=r"(u) : "f"(x));
    return __uint_as_float(u);
}

__device__ __forceinline__ void mma_tf32(float c[4], const unsigned a[4], const unsigned b[2]) {
    asm volatile(
        "mma.sync.aligned.m16n8k8.row.col.f32.tf32.tf32.f32 "
        "{%0,%1,%2,%3}, {%4,%5,%6,%7}, {%8,%9}, {%0,%1,%2,%3};"
        : "+f"(c[0]), "+f"(c[1]), "+f"(c[2]), "+f"(c[3])
        : "r"(a[0]), "r"(a[1]), "r"(a[2]), "r"(a[3]), "r"(b[0]), "r"(b[1]));
}

// ---------------- kernel 0: pack mask to bits ----------------
__global__ void maskpack_kernel(const int* __restrict__ mask) {
    int gtid = blockIdx.x * blockDim.x + threadIdx.x;
    int word = gtid >> 5;
    int lane = gtid & 31;
    if (word >= NB * SEQL * (SEQL / 32)) return;
    int m = mask[(long)word * 32 + lane];
    unsigned bits = __ballot_sync(0xFFFFFFFFu, m != 0);
    if (lane == 0) g_mbits[word] = bits;
}

// ---------------- kernel 1: fused per-head projections (tf32 mma) ----------------
// GEMM: M=65536, N=64, K=64. Block tile 128x64, 4 warps, warp = 32 rows (2 m-frags).
__global__ void __launch_bounds__(128) proj_kernel(
    const float* __restrict__ qsrc, const float* __restrict__ ksrc, const float* __restrict__ vsrc,
    const float* __restrict__ Wq, const float* __restrict__ Wk, const float* __restrict__ Wv)
{
    const int which = blockIdx.y;
    const float* __restrict__ x = (which == 0) ? qsrc : (which == 1) ? ksrc : vsrc;
    const float* __restrict__ W = (which == 0) ? Wq : (which == 1) ? Wk : Wv;
    float* __restrict__ dst = (which == 0) ? g_Q : (which == 1) ? g_K : g_V;

    const int mrow = blockIdx.x * 128;
    const int warp = threadIdx.x >> 5, lane = threadIdx.x & 31;
    const int g = lane >> 2, tg = lane & 3;

    __shared__ float Xs[128 * 68];
    __shared__ float Ws[64 * 68];
    const int STR = 68;

#pragma unroll
    for (int i = 0; i < 16; i++) {
        int f = threadIdx.x + i * 128;
        int row = f >> 4, c4 = (f & 15) << 2;
        float4 v = *(const float4*)(x + (long)(mrow + row) * 64 + c4);
        v.x = tf32r(v.x); v.y = tf32r(v.y); v.z = tf32r(v.z); v.w = tf32r(v.w);
        *(float4*)(&Xs[row * STR + c4]) = v;
    }
#pragma unroll
    for (int i = 0; i < 8; i++) {
        int f = threadIdx.x + i * 128;
        int row = f >> 4, c4 = (f & 15) << 2;
        float4 v = *(const float4*)(W + (long)row * 64 + c4);
        v.x = tf32r(v.x); v.y = tf32r(v.y); v.z = tf32r(v.z); v.w = tf32r(v.w);
        *(float4*)(&Ws[row * STR + c4]) = v;
    }
    __syncthreads();

    float acc[2][8][4] = {};
    const int br = warp * 32 + g;

#pragma unroll
    for (int kk = 0; kk < 8; kk++) {
        unsigned a0[4], a1[4];
        a0[0] = __float_as_uint(Xs[(br)      * STR + kk * 8 + tg]);
        a0[1] = __float_as_uint(Xs[(br + 8)  * STR + kk * 8 + tg]);
        a0[2] = __float_as_uint(Xs[(br)      * STR + kk * 8 + tg + 4]);
        a0[3] = __float_as_uint(Xs[(br + 8)  * STR + kk * 8 + tg + 4]);
        a1[0] = __float_as_uint(Xs[(br + 16) * STR + kk * 8 + tg]);
        a1[1] = __float_as_uint(Xs[(br + 24) * STR + kk * 8 + tg]);
        a1[2] = __float_as_uint(Xs[(br + 16) * STR + kk * 8 + tg + 4]);
        a1[3] = __float_as_uint(Xs[(br + 24) * STR + kk * 8 + tg + 4]);
#pragma unroll
        for (int nb = 0; nb < 8; nb++) {
            unsigned b[2];
            b[0] = __float_as_uint(Ws[(nb * 8 + g) * STR + kk * 8 + tg]);
            b[1] = __float_as_uint(Ws[(nb * 8 + g) * STR + kk * 8 + tg + 4]);
            mma_tf32(acc[0][nb], a0, b);
            mma_tf32(acc[1][nb], a1, b);
        }
    }

#pragma unroll
    for (int f = 0; f < 2; f++)
#pragma unroll
        for (int half = 0; half < 2; half++) {
            int r = mrow + br + 16 * f + 8 * half;
            int h = r & 15;
            int s = (r >> 4) & (SEQL - 1);
            int n = r >> 15;
            long ob = ((long)(n * HEADS + h) * SEQL + s) * 64;
#pragma unroll
            for (int nb = 0; nb < 8; nb++) {
                int c0 = nb * 8 + tg * 2;
                float2 v = make_float2(tf32r(acc[f][nb][2 * half]),
                                       tf32r(acc[f][nb][2 * half + 1]));
                *(float2*)(dst + ob + c0) = v;
            }
        }
}

// ---------------- kernel 2: flash attention (tf32 mma, cp.async double-buffer) ----------------
// grid: (16 q-tiles of 128, 16 heads, 2 batch); block: 128 threads (4 warps)
// warp w owns q-rows [w*32, w*32+32): two m16 fragments. k-tile = 32.
// K/V tiles stream via cp.async into alternating smem buffers; one sync per tile.
__global__ void __launch_bounds__(128) attn_kernel() {
    const int qt = blockIdx.x, h = blockIdx.y, n = blockIdx.z;
    const int warp = threadIdx.x >> 5, lane = threadIdx.x & 31;
    const int g = lane >> 2, tg = lane & 3;

    const int STRK = 68, STRV = 72, STRP = 36;
    __shared__ float Ks[2][32 * 68];   // K tile: 32 k-rows x 64 d, double-buffered
    __shared__ float Vs[2][32 * 72];   // V tile: 32 k-rows x 64 d, double-buffered
    __shared__ float Ps[128 * 36];     // P: 128 q-rows x 32 k-cols

    const float* __restrict__ Qg = g_Q + ((long)(n * HEADS + h) * SEQL + qt * 128) * 64;
    const float* __restrict__ Kg = g_K + (long)(n * HEADS + h) * SEQL * 64;
    const float* __restrict__ Vg = g_V + (long)(n * HEADS + h) * SEQL * 64;

    const int r0 = warp * 32 + g;

    // per-thread fill coordinates (4 float4 slots each for K and V)
    int frow[4], fc4[4];
#pragma unroll
    for (int i = 0; i < 4; i++) {
        int f = threadIdx.x + i * 128;      // 0..511
        frow[i] = f >> 4;
        fc4[i]  = (f & 15) << 2;
    }

    // Q fragments for 2 m-frags, register-resident across all k-tiles (64 regs)
    unsigned qa[2][8][4];
#pragma unroll
    for (int f = 0; f < 2; f++)
#pragma unroll
        for (int kk = 0; kk < 8; kk++) {
            int ra = r0 + 16 * f;
            qa[f][kk][0] = __float_as_uint(Qg[(long)(ra)     * 64 + kk * 8 + tg]);
            qa[f][kk][1] = __float_as_uint(Qg[(long)(ra + 8) * 64 + kk * 8 + tg]);
            qa[f][kk][2] = __float_as_uint(Qg[(long)(ra)     * 64 + kk * 8 + tg + 4]);
            qa[f][kk][3] = __float_as_uint(Qg[(long)(ra + 8) * 64 + kk * 8 + tg + 4]);
        }

    float o[2][8][4] = {};
    const float NEG = __int_as_float(0xff800000);  // -inf
    float mrun[4] = {NEG, NEG, NEG, NEG};          // rows r0, r0+8, r0+16, r0+24
    float lrun[4] = {0.f, 0.f, 0.f, 0.f};

    const unsigned* __restrict__ mbase =
        g_mbits + ((long)(n * SEQL + qt * 128 + r0)) * 64;

    const float SC = 0.03125f;           // 1/sqrt(1024)
    const float MASKED = -1e20f * SC;    // matches reference: (-1e20)/sqrt(1024)

    // prologue: issue async fill for tile 0
#pragma unroll
    for (int i = 0; i < 4; i++) {
        __pipeline_memcpy_async(&Ks[0][frow[i] * STRK + fc4[i]],
                                Kg + (long)frow[i] * 64 + fc4[i], 16);
        __pipeline_memcpy_async(&Vs[0][frow[i] * STRV + fc4[i]],
                                Vg + (long)frow[i] * 64 + fc4[i], 16);
    }
    __pipeline_commit();

    for (int kt = 0; kt < 64; kt++) {
        const int buf = kt & 1;
        __pipeline_wait_prior(0);
        __syncthreads();    // buffer 'buf' filled and visible to all warps

        // issue async fill for next tile into the other buffer (overlaps compute)
        if (kt + 1 < 64) {
            const float* Ksrc = Kg + (long)(kt + 1) * 32 * 64;
            const float* Vsrc = Vg + (long)(kt + 1) * 32 * 64;
#pragma unroll
            for (int i = 0; i < 4; i++) {
                __pipeline_memcpy_async(&Ks[buf ^ 1][frow[i] * STRK + fc4[i]],
                                        Ksrc + (long)frow[i] * 64 + fc4[i], 16);
                __pipeline_memcpy_async(&Vs[buf ^ 1][frow[i] * STRV + fc4[i]],
                                        Vsrc + (long)frow[i] * 64 + fc4[i], 16);
            }
            __pipeline_commit();
        }

        // mask words for this thread's 4 rows (tile = 32 cols = 1 word)
        unsigned mw[4];
#pragma unroll
        for (int j = 0; j < 4; j++) mw[j] = mbase[j * 8 * 64 + kt];

        // S = Q * K^T : 32 q-rows x 32 k-cols per warp; B reused across m-frags
        float s[2][4][4] = {};
#pragma unroll
        for (int kk = 0; kk < 8; kk++) {
#pragma unroll
            for (int nb = 0; nb < 4; nb++) {
                unsigned b[2];
                b[0] = __float_as_uint(Ks[buf][(nb * 8 + g) * STRK + kk * 8 + tg]);
                b[1] = __float_as_uint(Ks[buf][(nb * 8 + g) * STRK + kk * 8 + tg + 4]);
                mma_tf32(s[0][nb], qa[0][kk], b);
                mma_tf32(s[1][nb], qa[1][kk], b);
            }
        }

        // masked logits + tile row-max (row j: f=j>>1, slots (j&1)*2..+1)
        float tmax[4] = {NEG, NEG, NEG, NEG};
#pragma unroll
        for (int nb = 0; nb < 4; nb++) {
            int c0 = nb * 8 + tg * 2, c1 = c0 + 1;
#pragma unroll
            for (int j = 0; j < 4; j++) {
                int f = j >> 1, sl = (j & 1) * 2;
                s[f][nb][sl]     = ((mw[j] >> c0) & 1) ? s[f][nb][sl]     * SC : MASKED;
                s[f][nb][sl + 1] = ((mw[j] >> c1) & 1) ? s[f][nb][sl + 1] * SC : MASKED;
                tmax[j] = fmaxf(tmax[j], fmaxf(s[f][nb][sl], s[f][nb][sl + 1]));
            }
        }

        float alpha[4];
#pragma unroll
        for (int j = 0; j < 4; j++) {
            tmax[j] = fmaxf(tmax[j], __shfl_xor_sync(0xFFFFFFFFu, tmax[j], 1));
            tmax[j] = fmaxf(tmax[j], __shfl_xor_sync(0xFFFFFFFFu, tmax[j], 2));
            float mn = fmaxf(mrun[j], tmax[j]);
            alpha[j] = __expf(mrun[j] - mn);
            mrun[j] = mn;
        }

        // exponentiate + row sums
        float rs[4] = {0.f, 0.f, 0.f, 0.f};
#pragma unroll
        for (int nb = 0; nb < 4; nb++)
#pragma unroll
            for (int f = 0; f < 2; f++) {
                s[f][nb][0] = __expf(s[f][nb][0] - mrun[2 * f]);
                s[f][nb][1] = __expf(s[f][nb][1] - mrun[2 * f]);
                s[f][nb][2] = __expf(s[f][nb][2] - mrun[2 * f + 1]);
                s[f][nb][3] = __expf(s[f][nb][3] - mrun[2 * f + 1]);
                rs[2 * f]     += s[f][nb][0] + s[f][nb][1];
                rs[2 * f + 1] += s[f][nb][2] + s[f][nb][3];
            }
#pragma unroll
        for (int j = 0; j < 4; j++) {
            rs[j] += __shfl_xor_sync(0xFFFFFFFFu, rs[j], 1);
            rs[j] += __shfl_xor_sync(0xFFFFFFFFu, rs[j], 2);
            lrun[j] = lrun[j] * alpha[j] + rs[j];
        }

        // rescale O
#pragma unroll
        for (int f = 0; f < 2; f++)
#pragma unroll
            for (int nb = 0; nb < 8; nb++) {
                o[f][nb][0] *= alpha[2 * f];     o[f][nb][1] *= alpha[2 * f];
                o[f][nb][2] *= alpha[2 * f + 1]; o[f][nb][3] *= alpha[2 * f + 1];
            }

        // store P (warp-private rows -> only __syncwarp needed)
#pragma unroll
        for (int f = 0; f < 2; f++)
#pragma unroll
            for (int nb = 0; nb < 4; nb++) {
                int ra = r0 + 16 * f;
                int c0 = nb * 8 + tg * 2;
                *(float2*)(&Ps[(ra)     * STRP + c0]) = make_float2(tf32r(s[f][nb][0]), tf32r(s[f][nb][1]));
                *(float2*)(&Ps[(ra + 8) * STRP + c0]) = make_float2(tf32r(s[f][nb][2]), tf32r(s[f][nb][3]));
            }
        __syncwarp();

        // O += P * V : per warp 32 q-rows x 64 d, k-range 32
#pragma unroll
        for (int kk2 = 0; kk2 < 4; kk2++) {
            unsigned pa0[4], pa1[4];
            pa0[0] = __float_as_uint(Ps[(r0)      * STRP + kk2 * 8 + tg]);
            pa0[1] = __float_as_uint(Ps[(r0 + 8)  * STRP + kk2 * 8 + tg]);
            pa0[2] = __float_as_uint(Ps[(r0)      * STRP + kk2 * 8 + tg + 4]);
            pa0[3] = __float_as_uint(Ps[(r0 + 8)  * STRP + kk2 * 8 + tg + 4]);
            pa1[0] = __float_as_uint(Ps[(r0 + 16) * STRP + kk2 * 8 + tg]);
            pa1[1] = __float_as_uint(Ps[(r0 + 24) * STRP + kk2 * 8 + tg]);
            pa1[2] = __float_as_uint(Ps[(r0 + 16) * STRP + kk2 * 8 + tg + 4]);
            pa1[3] = __float_as_uint(Ps[(r0 + 24) * STRP + kk2 * 8 + tg + 4]);
#pragma unroll
            for (int nb = 0; nb < 8; nb++) {
                unsigned b[2];
                b[0] = __float_as_uint(Vs[buf][(kk2 * 8 + tg)     * STRV + nb * 8 + g]);
                b[1] = __float_as_uint(Vs[buf][(kk2 * 8 + tg + 4) * STRV + nb * 8 + g]);
                mma_tf32(o[0][nb], pa0, b);
                mma_tf32(o[1][nb], pa1, b);
            }
        }
        // no trailing sync: next iteration's wait+syncthreads orders buffer reuse
    }

    // epilogue: normalize, write att[n][q][h*64+d] (tf32-rounded for Wo GEMM)
    float inv[4];
#pragma unroll
    for (int j = 0; j < 4; j++) inv[j] = 1.0f / lrun[j];

    float* __restrict__ Og = g_att + ((long)n * SEQL + qt * 128) * EMB + h * 64;
#pragma unroll
    for (int f = 0; f < 2; f++)
#pragma unroll
        for (int nb = 0; nb < 8; nb++) {
            int ra = r0 + 16 * f;
            int c0 = nb * 8 + tg * 2;
            Og[(long)(ra)     * EMB + c0]     = tf32r(o[f][nb][0] * inv[2 * f]);
            Og[(long)(ra)     * EMB + c0 + 1] = tf32r(o[f][nb][1] * inv[2 * f]);
            Og[(long)(ra + 8) * EMB + c0]     = tf32r(o[f][nb][2] * inv[2 * f + 1]);
            Og[(long)(ra + 8) * EMB + c0 + 1] = tf32r(o[f][nb][3] * inv[2 * f + 1]);
        }
}

// ---------------- kernel 3: output projection (tf32 mma, m=32/warp) ----------------
__global__ void __launch_bounds__(128) wo_kernel(
    const float* __restrict__ Wo, const float* __restrict__ bo, float* __restrict__ out)
{
    const int mrow = blockIdx.x * 128;
    const int ecol = blockIdx.y * 64;
    const int warp = threadIdx.x >> 5, lane = threadIdx.x & 31;
    const int g = lane >> 2, tg = lane & 3;

    __shared__ float As[128 * 68];
    __shared__ float Bs[64 * 68];
    const int STR = 68;

    float acc[2][8][4] = {};
    const int br = warp * 32 + g;

    for (int kc = 0; kc < 16; kc++) {
#pragma unroll
        for (int i = 0; i < 16; i++) {
            int f = threadIdx.x + i * 128;
            int row = f >> 4, c4 = (f & 15) << 2;
            *(float4*)(&As[row * STR + c4]) =
                *(const float4*)(g_att + (long)(mrow + row) * EMB + kc * 64 + c4);
        }
#pragma unroll
        for (int i = 0; i < 8; i++) {
            int f = threadIdx.x + i * 128;
            int row = f >> 4, c4 = (f & 15) << 2;
            float4 bv = *(const float4*)(Wo + (long)(ecol + row) * EMB + kc * 64 + c4);
            bv.x = tf32r(bv.x); bv.y = tf32r(bv.y); bv.z = tf32r(bv.z); bv.w = tf32r(bv.w);
            *(float4*)(&Bs[row * STR + c4]) = bv;
        }
        __syncthreads();

#pragma unroll
        for (int kk = 0; kk < 8; kk++) {
            unsigned a0[4], a1[4];
            a0[0] = __float_as_uint(As[(br)      * STR + kk * 8 + tg]);
            a0[1] = __float_as_uint(As[(br + 8)  * STR + kk * 8 + tg]);
            a0[2] = __float_as_uint(As[(br)      * STR + kk * 8 + tg + 4]);
            a0[3] = __float_as_uint(As[(br + 8)  * STR + kk * 8 + tg + 4]);
            a1[0] = __float_as_uint(As[(br + 16) * STR + kk * 8 + tg]);
            a1[1] = __float_as_uint(As[(br + 24) * STR + kk * 8 + tg]);
            a1[2] = __float_as_uint(As[(br + 16) * STR + kk * 8 + tg + 4]);
            a1[3] = __float_as_uint(As[(br + 24) * STR + kk * 8 + tg + 4]);
#pragma unroll
            for (int nb = 0; nb < 8; nb++) {
                unsigned b[2];
                b[0] = __float_as_uint(Bs[(nb * 8 + g) * STR + kk * 8 + tg]);
                b[1] = __float_as_uint(Bs[(nb * 8 + g) * STR + kk * 8 + tg + 4]);
                mma_tf32(acc[0][nb], a0, b);
                mma_tf32(acc[1][nb], a1, b);
            }
        }
        __syncthreads();
    }

#pragma unroll
    for (int f = 0; f < 2; f++)
#pragma unroll
        for (int nb = 0; nb < 8; nb++) {
            int row = mrow + br + 16 * f;
            int e0 = ecol + nb * 8 + tg * 2;
            float b0 = bo[e0], b1 = bo[e0 + 1];
            out[(long)(row)     * EMB + e0]     = acc[f][nb][0] + b0;
            out[(long)(row)     * EMB + e0 + 1] = acc[f][nb][1] + b1;
            out[(long)(row + 8) * EMB + e0]     = acc[f][nb][2] + b0;
            out[(long)(row + 8) * EMB + e0 + 1] = acc[f][nb][3] + b1;
        }
}

// ---------------- launch ----------------
extern "C" void kernel_launch(void* const* d_in, const int* in_sizes, int n_in,
                              void* d_out, int out_size) {
    const float* vals = (const float*)d_in[0];
    const float* keys = (const float*)d_in[1];
    const float* qry  = (const float*)d_in[2];
    const int*   mask = (const int*)d_in[3];
    const float* Wv   = (const float*)d_in[4];
    const float* Wk   = (const float*)d_in[5];
    const float* Wq   = (const float*)d_in[6];
    const float* Wo   = (const float*)d_in[7];
    const float* bo   = (const float*)d_in[8];
    float* out = (float*)d_out;

    long total_threads = (long)NB * SEQL * SEQL;
    maskpack_kernel<<<(unsigned)((total_threads + 255) / 256), 256>>>(mask);

    proj_kernel<<<dim3(512, 3), 128>>>(qry, keys, vals, Wq, Wk, Wv);

    attn_kernel<<<dim3(SEQL / 128, HEADS, NB), 128>>>();

    wo_kernel<<<dim3((NB * SEQL) / 128, EMB / 64), 128>>>(Wo, bo, out);
}

// round 13
// speedup vs baseline: 1.6375x; 1.0811x over previous
#include <cuda_runtime.h>
#include <cuda_pipeline.h>
#include <cstdint>
#include <math.h>

#define NB    2
#define SEQL  2048
#define HEADS 16
#define HD    64
#define EMB   1024

// ---------------- scratch (device globals; no allocations) ----------------
__device__ float    g_Q[NB * HEADS * SEQL * HD];   // [n][h][s][d] tf32-rounded
__device__ float    g_K[NB * HEADS * SEQL * HD];
__device__ float    g_V[NB * HEADS * SEQL * HD];
__device__ float    g_att[NB * SEQL * EMB];        // [n][s][e] tf32-rounded
__device__ float    g_Wo[EMB * EMB];               // tf32-rounded Wo
__device__ unsigned g_mbits[NB * SEQL * (SEQL / 32)];

// log2(e) / sqrt(1024)
#define SCL2E 0.045084220027797920f

// ---------------- helpers ----------------
__device__ __forceinline__ float tf32r(float x) {
    unsigned u;
    asm("cvt.rna.tf32.f32 %0, %1;" : "=r"(u) : "f"(x));
    return __uint_as_float(u);
}

__device__ __forceinline__ void mma_tf32(float c[4], const unsigned a[4], const unsigned b[2]) {
    asm volatile(
        "mma.sync.aligned.m16n8k8.row.col.f32.tf32.tf32.f32 "
        "{%0,%1,%2,%3}, {%4,%5,%6,%7}, {%8,%9}, {%0,%1,%2,%3};"
        : "+f"(c[0]), "+f"(c[1]), "+f"(c[2]), "+f"(c[3])
        : "r"(a[0]), "r"(a[1]), "r"(a[2]), "r"(a[3]), "r"(b[0]), "r"(b[1]));
}

// ---------------- kernel 0: pack mask to bits ----------------
__global__ void maskpack_kernel(const int* __restrict__ mask) {
    int gtid = blockIdx.x * blockDim.x + threadIdx.x;
    int word = gtid >> 5;
    int lane = gtid & 31;
    if (word >= NB * SEQL * (SEQL / 32)) return;
    int m = mask[(long)word * 32 + lane];
    unsigned bits = __ballot_sync(0xFFFFFFFFu, m != 0);
    if (lane == 0) g_mbits[word] = bits;
}

// ---------------- kernel 0b: pre-round Wo to tf32 ----------------
__global__ void woround_kernel(const float* __restrict__ Wo) {
    int i = blockIdx.x * blockDim.x + threadIdx.x;   // float4 index
    float4 v = *(const float4*)(Wo + (long)i * 4);
    v.x = tf32r(v.x); v.y = tf32r(v.y); v.z = tf32r(v.z); v.w = tf32r(v.w);
    *(float4*)(g_Wo + (long)i * 4) = v;
}

// ---------------- kernel 1: fused per-head projections (tf32 mma) ----------------
// GEMM: M=65536, N=64, K=64. Block tile 128x64, 4 warps, warp = 32 rows (2 m-frags).
__global__ void __launch_bounds__(128) proj_kernel(
    const float* __restrict__ qsrc, const float* __restrict__ ksrc, const float* __restrict__ vsrc,
    const float* __restrict__ Wq, const float* __restrict__ Wk, const float* __restrict__ Wv)
{
    const int which = blockIdx.y;
    const float* __restrict__ x = (which == 0) ? qsrc : (which == 1) ? ksrc : vsrc;
    const float* __restrict__ W = (which == 0) ? Wq : (which == 1) ? Wk : Wv;
    float* __restrict__ dst = (which == 0) ? g_Q : (which == 1) ? g_K : g_V;

    const int mrow = blockIdx.x * 128;
    const int warp = threadIdx.x >> 5, lane = threadIdx.x & 31;
    const int g = lane >> 2, tg = lane & 3;

    __shared__ float Xs[128 * 68];
    __shared__ float Ws[64 * 68];
    const int STR = 68;

#pragma unroll
    for (int i = 0; i < 16; i++) {
        int f = threadIdx.x + i * 128;
        int row = f >> 4, c4 = (f & 15) << 2;
        float4 v = *(const float4*)(x + (long)(mrow + row) * 64 + c4);
        v.x = tf32r(v.x); v.y = tf32r(v.y); v.z = tf32r(v.z); v.w = tf32r(v.w);
        *(float4*)(&Xs[row * STR + c4]) = v;
    }
#pragma unroll
    for (int i = 0; i < 8; i++) {
        int f = threadIdx.x + i * 128;
        int row = f >> 4, c4 = (f & 15) << 2;
        float4 v = *(const float4*)(W + (long)row * 64 + c4);
        v.x = tf32r(v.x); v.y = tf32r(v.y); v.z = tf32r(v.z); v.w = tf32r(v.w);
        *(float4*)(&Ws[row * STR + c4]) = v;
    }
    __syncthreads();

    float acc[2][8][4] = {};
    const int br = warp * 32 + g;

#pragma unroll
    for (int kk = 0; kk < 8; kk++) {
        unsigned a0[4], a1[4];
        a0[0] = __float_as_uint(Xs[(br)      * STR + kk * 8 + tg]);
        a0[1] = __float_as_uint(Xs[(br + 8)  * STR + kk * 8 + tg]);
        a0[2] = __float_as_uint(Xs[(br)      * STR + kk * 8 + tg + 4]);
        a0[3] = __float_as_uint(Xs[(br + 8)  * STR + kk * 8 + tg + 4]);
        a1[0] = __float_as_uint(Xs[(br + 16) * STR + kk * 8 + tg]);
        a1[1] = __float_as_uint(Xs[(br + 24) * STR + kk * 8 + tg]);
        a1[2] = __float_as_uint(Xs[(br + 16) * STR + kk * 8 + tg + 4]);
        a1[3] = __float_as_uint(Xs[(br + 24) * STR + kk * 8 + tg + 4]);
#pragma unroll
        for (int nb = 0; nb < 8; nb++) {
            unsigned b[2];
            b[0] = __float_as_uint(Ws[(nb * 8 + g) * STR + kk * 8 + tg]);
            b[1] = __float_as_uint(Ws[(nb * 8 + g) * STR + kk * 8 + tg + 4]);
            mma_tf32(acc[0][nb], a0, b);
            mma_tf32(acc[1][nb], a1, b);
        }
    }

#pragma unroll
    for (int f = 0; f < 2; f++)
#pragma unroll
        for (int half = 0; half < 2; half++) {
            int r = mrow + br + 16 * f + 8 * half;
            int h = r & 15;
            int s = (r >> 4) & (SEQL - 1);
            int n = r >> 15;
            long ob = ((long)(n * HEADS + h) * SEQL + s) * 64;
#pragma unroll
            for (int nb = 0; nb < 8; nb++) {
                int c0 = nb * 8 + tg * 2;
                float2 v = make_float2(tf32r(acc[f][nb][2 * half]),
                                       tf32r(acc[f][nb][2 * half + 1]));
                *(float2*)(dst + ob + c0) = v;
            }
        }
}

// ---------------- kernel 2: flash attention ----------------
// grid: (16 q-tiles of 128, 16 heads, 2 batch); block: 128 threads (4 warps)
// warp w owns q-rows [w*32, w*32+32). k-tile = 64 (one barrier), processed as
// two 32-col softmax halves. cp.async double-buffered K/V. Raw running max as
// softmax reference (cancels in o/l); masked probs zeroed explicitly.
#define ATTN_SMEM_FLOATS (2 * 64 * 68 + 2 * 64 * 72 + 128 * 36)
__global__ void __launch_bounds__(128) attn_kernel() {
    const int qt = blockIdx.x, h = blockIdx.y, n = blockIdx.z;
    const int warp = threadIdx.x >> 5, lane = threadIdx.x & 31;
    const int g = lane >> 2, tg = lane & 3;

    extern __shared__ float smem[];
    const int STRK = 68, STRV = 72, STRP = 36;
    float* KsBase = smem;                              // [2][64*68]
    float* VsBase = smem + 2 * 64 * 68;                // [2][64*72]
    float* Ps     = smem + 2 * 64 * 68 + 2 * 64 * 72;  // [128*36]

    const float* __restrict__ Qg = g_Q + ((long)(n * HEADS + h) * SEQL + qt * 128) * 64;
    const float* __restrict__ Kg = g_K + (long)(n * HEADS + h) * SEQL * 64;
    const float* __restrict__ Vg = g_V + (long)(n * HEADS + h) * SEQL * 64;

    const int r0 = warp * 32 + g;

    // per-thread fill coordinates: 8 float4 slots each for K and V (64x16 slots)
    int frow[8], fc4[8];
#pragma unroll
    for (int i = 0; i < 8; i++) {
        int f = threadIdx.x + i * 128;      // 0..1023
        frow[i] = f >> 4;
        fc4[i]  = (f & 15) << 2;
    }

    // Q fragments for 2 m-frags, register-resident across all k-tiles (64 regs)
    unsigned qa[2][8][4];
#pragma unroll
    for (int f = 0; f < 2; f++)
#pragma unroll
        for (int kk = 0; kk < 8; kk++) {
            int ra = r0 + 16 * f;
            qa[f][kk][0] = __float_as_uint(Qg[(long)(ra)     * 64 + kk * 8 + tg]);
            qa[f][kk][1] = __float_as_uint(Qg[(long)(ra + 8) * 64 + kk * 8 + tg]);
            qa[f][kk][2] = __float_as_uint(Qg[(long)(ra)     * 64 + kk * 8 + tg + 4]);
            qa[f][kk][3] = __float_as_uint(Qg[(long)(ra + 8) * 64 + kk * 8 + tg + 4]);
        }

    float o[2][8][4] = {};
    const float NEG = __int_as_float(0xff800000);  // -inf
    float mrun[4] = {NEG, NEG, NEG, NEG};          // RAW running max, rows r0+{0,8,16,24}
    float lrun[4] = {0.f, 0.f, 0.f, 0.f};

    const unsigned* __restrict__ mbase =
        g_mbits + ((long)(n * SEQL + qt * 128 + r0)) * 64;

    // prologue: async fill tile 0 (64 k-rows of K and V)
#pragma unroll
    for (int i = 0; i < 8; i++) {
        __pipeline_memcpy_async(&KsBase[frow[i] * STRK + fc4[i]],
                                Kg + (long)frow[i] * 64 + fc4[i], 16);
        __pipeline_memcpy_async(&VsBase[frow[i] * STRV + fc4[i]],
                                Vg + (long)frow[i] * 64 + fc4[i], 16);
    }
    __pipeline_commit();

    for (int kt = 0; kt < 32; kt++) {
        const int buf = kt & 1;
        float* Ks = KsBase + buf * (64 * 68);
        float* Vs = VsBase + buf * (64 * 72);
        __pipeline_wait_prior(0);
        __syncthreads();

        // issue async fill for next 64-tile into the other buffer
        if (kt + 1 < 32) {
            float* Kd = KsBase + (buf ^ 1) * (64 * 68);
            float* Vd = VsBase + (buf ^ 1) * (64 * 72);
            const float* Ksrc = Kg + (long)(kt + 1) * 64 * 64;
            const float* Vsrc = Vg + (long)(kt + 1) * 64 * 64;
#pragma unroll
            for (int i = 0; i < 8; i++) {
                __pipeline_memcpy_async(&Kd[frow[i] * STRK + fc4[i]],
                                        Ksrc + (long)frow[i] * 64 + fc4[i], 16);
                __pipeline_memcpy_async(&Vd[frow[i] * STRV + fc4[i]],
                                        Vsrc + (long)frow[i] * 64 + fc4[i], 16);
            }
            __pipeline_commit();
        }

#pragma unroll
        for (int half = 0; half < 2; half++) {
            const int rb = half * 32;   // k-row offset within the 64-tile

            // mask words for this thread's 4 rows (32 cols = 1 word)
            unsigned mw[4];
#pragma unroll
            for (int j = 0; j < 4; j++) mw[j] = mbase[j * 8 * 64 + kt * 2 + half];

            // S = Q * K^T : 32 q-rows x 32 k-cols per warp (raw logits)
            float s[2][4][4] = {};
#pragma unroll
            for (int kk = 0; kk < 8; kk++) {
#pragma unroll
                for (int nb = 0; nb < 4; nb++) {
                    unsigned b[2];
                    b[0] = __float_as_uint(Ks[(rb + nb * 8 + g) * STRK + kk * 8 + tg]);
                    b[1] = __float_as_uint(Ks[(rb + nb * 8 + g) * STRK + kk * 8 + tg + 4]);
                    mma_tf32(s[0][nb], qa[0][kk], b);
                    mma_tf32(s[1][nb], qa[1][kk], b);
                }
            }

            // raw row-max (no mask select: raw max is a valid reference point)
            float tmax[4] = {NEG, NEG, NEG, NEG};
#pragma unroll
            for (int nb = 0; nb < 4; nb++)
#pragma unroll
                for (int j = 0; j < 4; j++) {
                    int f = j >> 1, sl = (j & 1) * 2;
                    tmax[j] = fmaxf(tmax[j], fmaxf(s[f][nb][sl], s[f][nb][sl + 1]));
                }

            float alpha[4];
#pragma unroll
            for (int j = 0; j < 4; j++) {
                tmax[j] = fmaxf(tmax[j], __shfl_xor_sync(0xFFFFFFFFu, tmax[j], 1));
                tmax[j] = fmaxf(tmax[j], __shfl_xor_sync(0xFFFFFFFFu, tmax[j], 2));
                float mn = fmaxf(mrun[j], tmax[j]);
                alpha[j] = exp2f((mrun[j] - mn) * SCL2E);
                mrun[j] = mn;
            }

            // p = exp2((s - mn)*SC*log2e), zero masked, accumulate row sums
            float rs[4] = {0.f, 0.f, 0.f, 0.f};
#pragma unroll
            for (int nb = 0; nb < 4; nb++) {
                int c0 = nb * 8 + tg * 2, c1 = c0 + 1;
#pragma unroll
                for (int j = 0; j < 4; j++) {
                    int f = j >> 1, sl = (j & 1) * 2;
                    float p0 = exp2f((s[f][nb][sl]     - mrun[j]) * SCL2E);
                    float p1 = exp2f((s[f][nb][sl + 1] - mrun[j]) * SCL2E);
                    p0 = ((mw[j] >> c0) & 1) ? p0 : 0.f;
                    p1 = ((mw[j] >> c1) & 1) ? p1 : 0.f;
                    s[f][nb][sl] = p0; s[f][nb][sl + 1] = p1;
                    rs[j] += p0 + p1;
                }
            }
#pragma unroll
            for (int j = 0; j < 4; j++) {
                rs[j] += __shfl_xor_sync(0xFFFFFFFFu, rs[j], 1);
                rs[j] += __shfl_xor_sync(0xFFFFFFFFu, rs[j], 2);
                lrun[j] = lrun[j] * alpha[j] + rs[j];
            }

            // rescale O only if some row's max moved (common case: skip)
            bool need = !(alpha[0] == 1.f && alpha[1] == 1.f &&
                          alpha[2] == 1.f && alpha[3] == 1.f);
            if (__any_sync(0xFFFFFFFFu, need)) {
#pragma unroll
                for (int f = 0; f < 2; f++)
#pragma unroll
                    for (int nb = 0; nb < 8; nb++) {
                        o[f][nb][0] *= alpha[2 * f];     o[f][nb][1] *= alpha[2 * f];
                        o[f][nb][2] *= alpha[2 * f + 1]; o[f][nb][3] *= alpha[2 * f + 1];
                    }
            }

            // store P (warp-private rows -> __syncwarp)
#pragma unroll
            for (int f = 0; f < 2; f++)
#pragma unroll
                for (int nb = 0; nb < 4; nb++) {
                    int ra = r0 + 16 * f;
                    int c0 = nb * 8 + tg * 2;
                    *(float2*)(&Ps[(ra)     * STRP + c0]) = make_float2(tf32r(s[f][nb][0]), tf32r(s[f][nb][1]));
                    *(float2*)(&Ps[(ra + 8) * STRP + c0]) = make_float2(tf32r(s[f][nb][2]), tf32r(s[f][nb][3]));
                }
            __syncwarp();

            // O += P * V : 32 q-rows x 64 d per warp, k-range 32
#pragma unroll
            for (int kk2 = 0; kk2 < 4; kk2++) {
                unsigned pa0[4], pa1[4];
                pa0[0] = __float_as_uint(Ps[(r0)      * STRP + kk2 * 8 + tg]);
                pa0[1] = __float_as_uint(Ps[(r0 + 8)  * STRP + kk2 * 8 + tg]);
                pa0[2] = __float_as_uint(Ps[(r0)      * STRP + kk2 * 8 + tg + 4]);
                pa0[3] = __float_as_uint(Ps[(r0 + 8)  * STRP + kk2 * 8 + tg + 4]);
                pa1[0] = __float_as_uint(Ps[(r0 + 16) * STRP + kk2 * 8 + tg]);
                pa1[1] = __float_as_uint(Ps[(r0 + 24) * STRP + kk2 * 8 + tg]);
                pa1[2] = __float_as_uint(Ps[(r0 + 16) * STRP + kk2 * 8 + tg + 4]);
                pa1[3] = __float_as_uint(Ps[(r0 + 24) * STRP + kk2 * 8 + tg + 4]);
#pragma unroll
                for (int nb = 0; nb < 8; nb++) {
                    unsigned b[2];
                    b[0] = __float_as_uint(Vs[(rb + kk2 * 8 + tg)     * STRV + nb * 8 + g]);
                    b[1] = __float_as_uint(Vs[(rb + kk2 * 8 + tg + 4) * STRV + nb * 8 + g]);
                    mma_tf32(o[0][nb], pa0, b);
                    mma_tf32(o[1][nb], pa1, b);
                }
            }
            __syncwarp();   // Ps reuse between halves is warp-private
        }
        // buffer reuse across tiles ordered by next iteration's wait+syncthreads
    }

    // epilogue: normalize, write att[n][q][h*64+d] (tf32-rounded for Wo GEMM)
    float inv[4];
#pragma unroll
    for (int j = 0; j < 4; j++) inv[j] = 1.0f / lrun[j];

    float* __restrict__ Og = g_att + ((long)n * SEQL + qt * 128) * EMB + h * 64;
#pragma unroll
    for (int f = 0; f < 2; f++)
#pragma unroll
        for (int nb = 0; nb < 8; nb++) {
            int ra = r0 + 16 * f;
            int c0 = nb * 8 + tg * 2;
            Og[(long)(ra)     * EMB + c0]     = tf32r(o[f][nb][0] * inv[2 * f]);
            Og[(long)(ra)     * EMB + c0 + 1] = tf32r(o[f][nb][1] * inv[2 * f]);
            Og[(long)(ra + 8) * EMB + c0]     = tf32r(o[f][nb][2] * inv[2 * f + 1]);
            Og[(long)(ra + 8) * EMB + c0 + 1] = tf32r(o[f][nb][3] * inv[2 * f + 1]);
        }
}

// ---------------- kernel 3: output projection (cp.async double-buffer) ----------------
// out[m][e] = sum_k att[m][k] * g_Wo[e][k] + bo[e];  M=4096, N=1024, K=1024
// k-chunks of 32, double-buffered; inputs pre-rounded (no in-loop cvt).
#define WO_SMEM_FLOATS (2 * 128 * 36 + 2 * 64 * 36)
__global__ void __launch_bounds__(128) wo_kernel(
    const float* __restrict__ bo, float* __restrict__ out)
{
    const int mrow = blockIdx.x * 128;
    const int ecol = blockIdx.y * 64;
    const int warp = threadIdx.x >> 5, lane = threadIdx.x & 31;
    const int g = lane >> 2, tg = lane & 3;

    extern __shared__ float smem[];
    const int STR = 36;
    float* AsBase = smem;                 // [2][128*36]
    float* BsBase = smem + 2 * 128 * 36;  // [2][64*36]

    // fill coords: As 128x8 float4-slots (1024 -> 8/thread), Bs 512 -> 4/thread
    int arow[8], ac4[8], brow[4], bc4[4];
#pragma unroll
    for (int i = 0; i < 8; i++) {
        int f = threadIdx.x + i * 128;
        arow[i] = f >> 3;  ac4[i] = (f & 7) << 2;
    }
#pragma unroll
    for (int i = 0; i < 4; i++) {
        int f = threadIdx.x + i * 128;
        brow[i] = f >> 3;  bc4[i] = (f & 7) << 2;
    }

    float acc[2][8][4] = {};
    const int br = warp * 32 + g;

    // prologue: fill chunk 0
#pragma unroll
    for (int i = 0; i < 8; i++)
        __pipeline_memcpy_async(&AsBase[arow[i] * STR + ac4[i]],
                                g_att + (long)(mrow + arow[i]) * EMB + ac4[i], 16);
#pragma unroll
    for (int i = 0; i < 4; i++)
        __pipeline_memcpy_async(&BsBase[brow[i] * STR + bc4[i]],
                                g_Wo + (long)(ecol + brow[i]) * EMB + bc4[i], 16);
    __pipeline_commit();

    for (int kc = 0; kc < 32; kc++) {
        const int buf = kc & 1;
        float* As = AsBase + buf * (128 * 36);
        float* Bs = BsBase + buf * (64 * 36);
        __pipeline_wait_prior(0);
        __syncthreads();

        if (kc + 1 < 32) {
            float* Ad = AsBase + (buf ^ 1) * (128 * 36);
            float* Bd = BsBase + (buf ^ 1) * (64 * 36);
            int kb = (kc + 1) * 32;
#pragma unroll
            for (int i = 0; i < 8; i++)
                __pipeline_memcpy_async(&Ad[arow[i] * STR + ac4[i]],
                                        g_att + (long)(mrow + arow[i]) * EMB + kb + ac4[i], 16);
#pragma unroll
            for (int i = 0; i < 4; i++)
                __pipeline_memcpy_async(&Bd[brow[i] * STR + bc4[i]],
                                        g_Wo + (long)(ecol + brow[i]) * EMB + kb + bc4[i], 16);
            __pipeline_commit();
        }

#pragma unroll
        for (int kk = 0; kk < 4; kk++) {
            unsigned a0[4], a1[4];
            a0[0] = __float_as_uint(As[(br)      * STR + kk * 8 + tg]);
            a0[1] = __float_as_uint(As[(br + 8)  * STR + kk * 8 + tg]);
            a0[2] = __float_as_uint(As[(br)      * STR + kk * 8 + tg + 4]);
            a0[3] = __float_as_uint(As[(br + 8)  * STR + kk * 8 + tg + 4]);
            a1[0] = __float_as_uint(As[(br + 16) * STR + kk * 8 + tg]);
            a1[1] = __float_as_uint(As[(br + 24) * STR + kk * 8 + tg]);
            a1[2] = __float_as_uint(As[(br + 16) * STR + kk * 8 + tg + 4]);
            a1[3] = __float_as_uint(As[(br + 24) * STR + kk * 8 + tg + 4]);
#pragma unroll
            for (int nb = 0; nb < 8; nb++) {
                unsigned b[2];
                b[0] = __float_as_uint(Bs[(nb * 8 + g) * STR + kk * 8 + tg]);
                b[1] = __float_as_uint(Bs[(nb * 8 + g) * STR + kk * 8 + tg + 4]);
                mma_tf32(acc[0][nb], a0, b);
                mma_tf32(acc[1][nb], a1, b);
            }
        }
    }

#pragma unroll
    for (int f = 0; f < 2; f++)
#pragma unroll
        for (int nb = 0; nb < 8; nb++) {
            int row = mrow + br + 16 * f;
            int e0 = ecol + nb * 8 + tg * 2;
            float b0 = bo[e0], b1 = bo[e0 + 1];
            out[(long)(row)     * EMB + e0]     = acc[f][nb][0] + b0;
            out[(long)(row)     * EMB + e0 + 1] = acc[f][nb][1] + b1;
            out[(long)(row + 8) * EMB + e0]     = acc[f][nb][2] + b0;
            out[(long)(row + 8) * EMB + e0 + 1] = acc[f][nb][3] + b1;
        }
}

// ---------------- launch ----------------
extern "C" void kernel_launch(void* const* d_in, const int* in_sizes, int n_in,
                              void* d_out, int out_size) {
    const float* vals = (const float*)d_in[0];
    const float* keys = (const float*)d_in[1];
    const float* qry  = (const float*)d_in[2];
    const int*   mask = (const int*)d_in[3];
    const float* Wv   = (const float*)d_in[4];
    const float* Wk   = (const float*)d_in[5];
    const float* Wq   = (const float*)d_in[6];
    const float* Wo   = (const float*)d_in[7];
    const float* bo   = (const float*)d_in[8];
    float* out = (float*)d_out;

    const int attn_smem = ATTN_SMEM_FLOATS * 4;   // 90112 B
    const int wo_smem   = WO_SMEM_FLOATS * 4;     // 55296 B
    cudaFuncSetAttribute(attn_kernel, cudaFuncAttributeMaxDynamicSharedMemorySize, attn_smem);
    cudaFuncSetAttribute(wo_kernel,   cudaFuncAttributeMaxDynamicSharedMemorySize, wo_smem);

    long total_threads = (long)NB * SEQL * SEQL;
    maskpack_kernel<<<(unsigned)((total_threads + 255) / 256), 256>>>(mask);

    woround_kernel<<<(EMB * EMB / 4) / 256, 256>>>(Wo);

    proj_kernel<<<dim3(512, 3), 128>>>(qry, keys, vals, Wq, Wk, Wv);

    attn_kernel<<<dim3(SEQL / 128, HEADS, NB), 128, attn_smem>>>();

    wo_kernel<<<dim3((NB * SEQL) / 128, EMB / 64), 128, wo_smem>>>(bo, out);
}